// round 8
// baseline (speedup 1.0000x reference)
#include <cuda_runtime.h>
#include <cuda_fp16.h>
#include <cstdint>
#include <math.h>

// ---------------- problem constants ----------------
#define BZ      2
#define LSEQ    4096
#define DMODEL  1024
#define DINNER  2048
#define NH      16
#define HD      128
#define DS      64
#define CHUNKT  256
#define NCHUNK  16
#define CONVDIM 2176
#define DPROJ   4240          // DINNER + CONVDIM + NH
#define MROWS   (BZ*LSEQ)     // 8192
#define NPAD1   4352          // ceil(4240/256)*256

// ---------------- scratch (device globals; allocation-free) ----------------
__device__ float g_proj[(size_t)MROWS * DPROJ];
__device__ float g_xbc [(size_t)MROWS * CONVDIM];
__device__ float g_dt  [MROWS * NH];
__device__ float g_Acs [BZ * NCHUNK * NH * CHUNKT];
__device__ float g_states[BZ * NCHUNK * NH * HD * DS];
__device__ float g_prevs [BZ * NCHUNK * NH * HD * DS];
__device__ __half g_a3[(size_t)MROWS * 3 * 2048];               // GEMM A, fp16 triple
__device__ __half g_b3[(size_t)NPAD1 * 3 * 1024];               // GEMM B, fp16 triple

__device__ __forceinline__ uint32_t smem_u32(const void* p) {
    uint32_t a;
    asm("{ .reg .u64 t; cvta.to.shared.u64 t, %1; cvt.u32.u64 %0, t; }" : "=r"(a) : "l"(p));
    return a;
}
__device__ __forceinline__ void cp16(uint32_t dst, const void* src) {
    asm volatile("cp.async.cg.shared.global [%0], [%1], 16;" :: "r"(dst), "l"(src));
}
__device__ __forceinline__ void cp_commit() { asm volatile("cp.async.commit_group;"); }
template<int NN> __device__ __forceinline__ void cp_wait() {
    asm volatile("cp.async.wait_group %0;" :: "n"(NN));
}
__device__ __forceinline__ void ldmx4(uint32_t addr, uint32_t& r0, uint32_t& r1,
                                      uint32_t& r2, uint32_t& r3) {
    asm volatile("ldmatrix.sync.aligned.m8n8.x4.shared.b16 {%0,%1,%2,%3}, [%4];"
        : "=r"(r0), "=r"(r1), "=r"(r2), "=r"(r3) : "r"(addr));
}
__device__ __forceinline__ void mma16816(float* c, const uint32_t* a, uint32_t b0, uint32_t b1) {
    asm volatile("mma.sync.aligned.m16n8k16.row.col.f32.f16.f16.f32 "
        "{%0,%1,%2,%3}, {%4,%5,%6,%7}, {%8,%9}, {%0,%1,%2,%3};"
        : "+f"(c[0]), "+f"(c[1]), "+f"(c[2]), "+f"(c[3])
        : "r"(a[0]), "r"(a[1]), "r"(a[2]), "r"(a[3]), "r"(b0), "r"(b1));
}
__device__ __forceinline__ void hsplit(float v, __half& h, __half& l) {
    h = __float2half_rn(v);
    l = __float2half_rn(v - __half2float(h));
}

#define ROWB 144   // padded smem row stride for 64-half rows (SSD kernels)

// ---------------- fp32 -> fp16 hi/lo split, K tripled ----------------
// isB=0 (A side): [Ah | Ah | Al]   isB=1 (B side): [Bh | Bl | Bh]
__global__ __launch_bounds__(256) void k_cvt3(
    const float4* __restrict__ src, __half* __restrict__ dst,
    int R, int K, int Rpad, int isB)
{
    int kw = K >> 2;
    int idx = blockIdx.x * 256 + threadIdx.x;
    if (idx >= Rpad * kw) return;
    int r = idx / kw, k4 = idx - r * kw;
    float4 v = make_float4(0.f, 0.f, 0.f, 0.f);
    if (r < R) v = src[(size_t)r * kw + k4];
    __half h0, l0h, h1, l1h, h2, l2h, h3, l3h;
    hsplit(v.x, h0, l0h); hsplit(v.y, h1, l1h);
    hsplit(v.z, h2, l2h); hsplit(v.w, h3, l3h);
    __half2 H0 = __halves2half2(h0, h1), H1 = __halves2half2(h2, h3);
    __half2 L0 = __halves2half2(l0h, l1h), L1 = __halves2half2(l2h, l3h);
    size_t base = (size_t)r * 3 * K + 4 * k4;
    __half2* d0 = (__half2*)(dst + base);
    __half2* d1 = (__half2*)(dst + base + K);
    __half2* d2 = (__half2*)(dst + base + 2 * K);
    d0[0] = H0; d0[1] = H1;
    if (isB) { d1[0] = L0; d1[1] = L1; d2[0] = H0; d2[1] = H1; }
    else     { d1[0] = H0; d1[1] = H1; d2[0] = L0; d2[1] = L1; }
}

// ---------------- HMMA GEMM (NT): C[M,N] = A[M,K3] * B[N,K3]^T ----------------
// 128(M) x 256(N) CTA tile, BK=32 halves, 4-stage cp.async pipeline,
// 8 warps of 64x64 (warp grid 2 M x 4 N).
#define GPADB 80                         // bytes per smem row (40 halves)
#define GSTGA 10240                      // A stage: 128 rows * 80B
#define GSTGB2 20480                     // B stage: 256 rows * 80B
#define GSTG  (GSTGA + GSTGB2)           // 30720 per stage
#define GSMEM (4 * GSTG)                 // 122880

__global__ __launch_bounds__(256) void gemm_h3(
    const __half* __restrict__ A, const __half* __restrict__ B,
    float* __restrict__ C, int M, int N, int K3)
{
    extern __shared__ __align__(16) char smem_raw[];
    uint32_t sb = smem_u32(smem_raw);
    const int tid = threadIdx.x;
    const int wid = tid >> 5, lane = tid & 31;
    const int m0 = blockIdx.y * 128, n0 = blockIdx.x * 256;
    const int KT = K3 >> 5;
    const int wm = (wid >> 2) * 64, wn = (wid & 3) * 64;

    const int lrow = tid >> 1;                 // 0..127 (A rows)
    const int lseg0 = (tid & 1) * 2;

    float acc[4][8][4];
#pragma unroll
    for (int a = 0; a < 4; a++)
#pragma unroll
        for (int b = 0; b < 8; b++)
#pragma unroll
            for (int c = 0; c < 4; c++) acc[a][b][c] = 0.f;

    auto load_stage = [&](int kt) {
        uint32_t sA = sb + (kt & 3) * GSTG;
        uint32_t sB = sA + GSTGA;
        const __half* ga = A + (size_t)(m0 + lrow) * K3 + kt * 32;
        const __half* gb = B + (size_t)(n0 + tid) * K3 + kt * 32;
#pragma unroll
        for (int s = 0; s < 2; s++)
            cp16(sA + lrow * GPADB + (lseg0 + s) * 16, ga + (lseg0 + s) * 8);
#pragma unroll
        for (int s = 0; s < 4; s++)
            cp16(sB + tid * GPADB + s * 16, gb + s * 8);
    };

    load_stage(0); cp_commit();
    load_stage(1); cp_commit();
    load_stage(2); cp_commit();

    for (int kt = 0; kt < KT; kt++) {
        cp_wait<2>();
        __syncthreads();
        if (kt + 3 < KT) load_stage(kt + 3);
        cp_commit();
        uint32_t sA = sb + (kt & 3) * GSTG;
        uint32_t sB = sA + GSTGA;
#pragma unroll
        for (int kk = 0; kk < 2; kk++) {
            uint32_t a[4][4], b[8][2];
#pragma unroll
            for (int mt = 0; mt < 4; mt++) {
                uint32_t addr = sA + (wm + mt * 16 + (lane & 15)) * GPADB
                              + (kk * 16 + (lane >> 4) * 8) * 2;
                ldmx4(addr, a[mt][0], a[mt][1], a[mt][2], a[mt][3]);
            }
#pragma unroll
            for (int nt2 = 0; nt2 < 4; nt2++) {
                uint32_t r0, r1, r2, r3;
                int n = wn + nt2 * 16 + (lane & 7) + ((lane >> 4) & 1) * 8;
                int kc = kk * 16 + ((lane >> 3) & 1) * 8;
                ldmx4(sB + n * GPADB + kc * 2, r0, r1, r2, r3);
                b[nt2*2][0] = r0; b[nt2*2][1] = r1;
                b[nt2*2+1][0] = r2; b[nt2*2+1][1] = r3;
            }
#pragma unroll
            for (int mt = 0; mt < 4; mt++)
#pragma unroll
                for (int nt = 0; nt < 8; nt++)
                    mma16816(acc[mt][nt], a[mt], b[nt][0], b[nt][1]);
        }
    }

#pragma unroll
    for (int mt = 0; mt < 4; mt++) {
        int r0 = m0 + wm + mt * 16 + (lane >> 2);
#pragma unroll
        for (int nt = 0; nt < 8; nt++) {
            int cb = n0 + wn + nt * 8 + (lane & 3) * 2;
            if (cb < N) {
                *(float2*)(C + (size_t)r0 * N + cb) =
                    make_float2(acc[mt][nt][0], acc[mt][nt][1]);
                *(float2*)(C + (size_t)(r0 + 8) * N + cb) =
                    make_float2(acc[mt][nt][2], acc[mt][nt][3]);
            }
        }
    }
}

// ---------------- depthwise causal conv (D_CONV=4) + bias + SiLU ----------------
__global__ __launch_bounds__(128) void k_conv(
    const float* __restrict__ cw, const float* __restrict__ cb)
{
    int c = blockIdx.x * 128 + threadIdx.x;
    int b = blockIdx.z;
    int l0 = blockIdx.y * 64;
    float w0 = cw[c*4+0], w1 = cw[c*4+1], w2 = cw[c*4+2], w3 = cw[c*4+3];
    float bias = cb[c];
    const float* pp = g_proj + (size_t)b * LSEQ * DPROJ + DINNER + c;
    float* op = g_xbc + (size_t)b * LSEQ * CONVDIM + c;
    float xm3 = 0.f, xm2 = 0.f, xm1 = 0.f;
    if (l0 >= 3) {
        xm3 = pp[(size_t)(l0-3) * DPROJ];
        xm2 = pp[(size_t)(l0-2) * DPROJ];
        xm1 = pp[(size_t)(l0-1) * DPROJ];
    }
#pragma unroll 4
    for (int i = 0; i < 64; i++) {
        int l = l0 + i;
        float xc = pp[(size_t)l * DPROJ];
        float s = w3*xc + w2*xm1 + w1*xm2 + w0*xm3 + bias;
        float sig = 1.f / (1.f + expf(-s));
        op[(size_t)l * CONVDIM] = s * sig;
        xm3 = xm2; xm2 = xm1; xm1 = xc;
    }
}

// ---------------- dt = softplus(...) fused with per-chunk cumsum of dt*A ----------------
__global__ __launch_bounds__(256) void k_dtacs(
    const float* __restrict__ dt_bias, const float* __restrict__ A_log)
{
    int blk = blockIdx.x;
    int h = blk & 15, c = (blk >> 4) & 15, b = blk >> 8;
    int t = threadIdx.x;
    int m = b * LSEQ + c * CHUNKT + t;
    float v = g_proj[(size_t)m * DPROJ + (DINNER + CONVDIM) + h] + dt_bias[h];
    float dt = (v > 20.f) ? v : log1pf(expf(v));
    g_dt[m * NH + h] = dt;
    float A = -expf(A_log[h]);
    __shared__ float s[CHUNKT];
    s[t] = dt * A;
    __syncthreads();
    for (int off = 1; off < CHUNKT; off <<= 1) {
        float u = (t >= off) ? s[t - off] : 0.f;
        __syncthreads();
        s[t] += u;
        __syncthreads();
    }
    g_Acs[blk * CHUNKT + t] = s[t];
}

// ---------------- per-chunk states (HMMA): S[p,n] = sum_k x[k,p]*w[k]*B[k,n] ----------------
#define ST_XH 0
#define ST_XL 18432
#define ST_BH 36864
#define ST_BL 46080
#define ST_SC 55296
#define ST_SMEM 56320

__global__ __launch_bounds__(256) void k_states()
{
    extern __shared__ __align__(16) char sm9[];
    const uint32_t sb = smem_u32(sm9);
    float* sc = (float*)(sm9 + ST_SC);
    int blk = blockIdx.x;
    int h = blk & 15, c = (blk >> 4) & 15, b = blk >> 8;
    int t = threadIdx.x;
    int wid = t >> 5, lane = t & 31;
    int m0 = b * LSEQ + c * CHUNKT;
    float aL = g_Acs[blk * CHUNKT + 255];
    sc[t] = g_dt[(m0 + t) * NH + h] * __expf(aL - g_Acs[blk * CHUNKT + t]);

    const int pr0 = wid * 16;                 // S row tile (p)
    float acc[8][4];
#pragma unroll
    for (int i = 0; i < 8; i++)
#pragma unroll
        for (int j = 0; j < 4; j++) acc[i][j] = 0.f;

    for (int kt = 0; kt < 4; kt++) {
        int k0 = kt * 64;
        __syncthreads();
        for (int i = t; i < 64*128; i += 256) {
            int r = i >> 7, p = i & 127;
            float v = g_xbc[(size_t)(m0 + k0 + r) * CONVDIM + h*HD + p];
            __half hh, ll; hsplit(v, hh, ll);
            *(__half*)(sm9 + ST_XH + p*ROWB + r*2) = hh;
            *(__half*)(sm9 + ST_XL + p*ROWB + r*2) = ll;
        }
        for (int i = t; i < 64*64; i += 256) {
            int r = i >> 6, n = i & 63;
            float v = g_xbc[(size_t)(m0 + k0 + r) * CONVDIM + DINNER + n] * sc[k0 + r];
            __half hh, ll; hsplit(v, hh, ll);
            *(__half*)(sm9 + ST_BH + n*ROWB + r*2) = hh;
            *(__half*)(sm9 + ST_BL + n*ROWB + r*2) = ll;
        }
        __syncthreads();
#pragma unroll
        for (int kk = 0; kk < 4; kk++) {
            uint32_t aH[4], aL4[4];
            uint32_t aoff = (pr0 + (lane & 15)) * ROWB + (kk*16 + (lane >> 4)*8) * 2;
            ldmx4(sb + ST_XH + aoff, aH[0], aH[1], aH[2], aH[3]);
            ldmx4(sb + ST_XL + aoff, aL4[0], aL4[1], aL4[2], aL4[3]);
            uint32_t bH[8][2], bL[8][2];
#pragma unroll
            for (int nt2 = 0; nt2 < 4; nt2++) {
                uint32_t boff = (nt2*16 + (lane & 7) + ((lane >> 4) & 1)*8) * ROWB
                              + (kk*16 + ((lane >> 3) & 1)*8) * 2;
                uint32_t r0, r1, r2, r3;
                ldmx4(sb + ST_BH + boff, r0, r1, r2, r3);
                bH[nt2*2][0]=r0; bH[nt2*2][1]=r1; bH[nt2*2+1][0]=r2; bH[nt2*2+1][1]=r3;
                ldmx4(sb + ST_BL + boff, r0, r1, r2, r3);
                bL[nt2*2][0]=r0; bL[nt2*2][1]=r1; bL[nt2*2+1][0]=r2; bL[nt2*2+1][1]=r3;
            }
#pragma unroll
            for (int nt = 0; nt < 8; nt++) {
                mma16816(acc[nt], aH,  bH[nt][0], bH[nt][1]);
                mma16816(acc[nt], aH,  bL[nt][0], bL[nt][1]);
                mma16816(acc[nt], aL4, bH[nt][0], bH[nt][1]);
            }
        }
    }
    int base = blk * HD * DS;
    int rL = lane >> 2, cc = (lane & 3) * 2;
#pragma unroll
    for (int e = 0; e < 2; e++) {
        int p = pr0 + rL + e*8;
#pragma unroll
        for (int nt = 0; nt < 8; nt++) {
            int n = nt*8 + cc;
            *(float2*)&g_states[base + p*DS + n] =
                make_float2(acc[nt][e*2], acc[nt][e*2+1]);
        }
    }
}

// ---------------- inter-chunk sequential scan ----------------
__global__ __launch_bounds__(256) void k_scan()
{
    int b = blockIdx.x >> 4, h = blockIdx.x & 15;
    int t = threadIdx.x;
    float prev[32];
#pragma unroll
    for (int j = 0; j < 32; j++) prev[j] = 0.f;
    for (int c = 0; c < NCHUNK; c++) {
        int bch = (b * NCHUNK + c) * NH + h;
        int base = bch * HD * DS;
#pragma unroll
        for (int j = 0; j < 32; j++) g_prevs[base + j*256 + t] = prev[j];
        float e = __expf(g_Acs[bch * CHUNKT + 255]);
#pragma unroll
        for (int j = 0; j < 32; j++)
            prev[j] = e * prev[j] + g_states[base + j*256 + t];
    }
}

// ---------------- fused HMMA: Y_diag + Y_off + D-skip + gate -> fp16 triple ----------------
#define SD_CH  0
#define SD_CL  9216
#define SD_BH  18432
#define SD_BL  27648
#define SD_XH  36864
#define SD_XL  55296
#define SD_GH  73728
#define SD_GL  82944
#define SD_ACS 92160
#define SD_DTS 93184
#define SD_SMEM 94208
// Pv (128x64) overlays XH/XL; consumed in phase1 before k-tile staging overwrites them.

__global__ __launch_bounds__(256) void k_ssdout(const float* __restrict__ D_skip)
{
    extern __shared__ __align__(16) char sm8[];
    const uint32_t sb = smem_u32(sm8);
    float* acs = (float*)(sm8 + SD_ACS);
    float* dts = (float*)(sm8 + SD_DTS);

    int blk = blockIdx.x;             // 2048
    int qb = blk & 3;
    int bch = blk >> 2;
    int h = bch & 15, c = (bch >> 4) & 15, b = bch >> 8;
    int t = threadIdx.x;
    int wid = t >> 5, lane = t & 31;
    int m0 = b * LSEQ + c * CHUNKT;
    int q0 = qb * 64;

    acs[t] = g_Acs[bch * CHUNKT + t];
    dts[t] = g_dt[(m0 + t) * NH + h];
    for (int i = t; i < 64*64; i += 256) {
        int q = i >> 6, n = i & 63;
        float v = g_xbc[(size_t)(m0 + q0 + q) * CONVDIM + (DINNER + DS) + n];
        __half hh, ll; hsplit(v, hh, ll);
        *(__half*)(sm8 + SD_CH + q*ROWB + n*2) = hh;
        *(__half*)(sm8 + SD_CL + q*ROWB + n*2) = ll;
    }
    for (int i = t; i < 128*64; i += 256) {
        int p = i >> 6, n = i & 63;
        float v = g_prevs[bch * HD * DS + p*DS + n];
        __half hh, ll; hsplit(v, hh, ll);
        *(__half*)(sm8 + SD_XH + p*ROWB + n*2) = hh;
        *(__half*)(sm8 + SD_XL + p*ROWB + n*2) = ll;
    }
    __syncthreads();

    const int yr0 = (wid >> 1) * 16;
    const int yc0 = (wid & 1) * 64;
    float accY[8][4];
#pragma unroll
    for (int i = 0; i < 8; i++)
#pragma unroll
        for (int j = 0; j < 4; j++) accY[i][j] = 0.f;

    // ---- phase 1: Y = C @ Pv^T ----
#pragma unroll
    for (int kk = 0; kk < 4; kk++) {
        uint32_t aH[4], aL4[4];
        uint32_t aoff = (yr0 + (lane & 15)) * ROWB + (kk*16 + (lane >> 4)*8) * 2;
        ldmx4(sb + SD_CH + aoff, aH[0], aH[1], aH[2], aH[3]);
        ldmx4(sb + SD_CL + aoff, aL4[0], aL4[1], aL4[2], aL4[3]);
        uint32_t bH[8][2], bL[8][2];
#pragma unroll
        for (int nt2 = 0; nt2 < 4; nt2++) {
            uint32_t boff = (yc0 + nt2*16 + (lane & 7) + ((lane >> 4) & 1)*8) * ROWB
                          + (kk*16 + ((lane >> 3) & 1)*8) * 2;
            uint32_t r0, r1, r2, r3;
            ldmx4(sb + SD_XH + boff, r0, r1, r2, r3);
            bH[nt2*2][0]=r0; bH[nt2*2][1]=r1; bH[nt2*2+1][0]=r2; bH[nt2*2+1][1]=r3;
            ldmx4(sb + SD_XL + boff, r0, r1, r2, r3);
            bL[nt2*2][0]=r0; bL[nt2*2][1]=r1; bL[nt2*2+1][0]=r2; bL[nt2*2+1][1]=r3;
        }
#pragma unroll
        for (int nt = 0; nt < 8; nt++) {
            mma16816(accY[nt], aH,  bH[nt][0], bH[nt][1]);
            mma16816(accY[nt], aH,  bL[nt][0], bL[nt][1]);
            mma16816(accY[nt], aL4, bH[nt][0], bH[nt][1]);
        }
    }
    {
        float e0 = __expf(acs[q0 + yr0 + (lane >> 2)]);
        float e1 = __expf(acs[q0 + yr0 + (lane >> 2) + 8]);
#pragma unroll
        for (int nt = 0; nt < 8; nt++) {
            accY[nt][0] *= e0; accY[nt][1] *= e0;
            accY[nt][2] *= e1; accY[nt][3] *= e1;
        }
    }

    // ---- phase 2: Y_diag over k-tiles ----
    const int gr0 = yr0, gc0 = (wid & 1) * 32;
    for (int kt = 0; kt <= qb; kt++) {
        int k0 = kt * 64;
        __syncthreads();
        for (int i = t; i < 64*64; i += 256) {
            int r = i >> 6, n = i & 63;
            float v = g_xbc[(size_t)(m0 + k0 + r) * CONVDIM + DINNER + n];
            __half hh, ll; hsplit(v, hh, ll);
            *(__half*)(sm8 + SD_BH + r*ROWB + n*2) = hh;
            *(__half*)(sm8 + SD_BL + r*ROWB + n*2) = ll;
        }
        for (int i = t; i < 64*128; i += 256) {
            int r = i >> 7, p = i & 127;
            float v = g_xbc[(size_t)(m0 + k0 + r) * CONVDIM + h*HD + p];
            __half hh, ll; hsplit(v, hh, ll);
            *(__half*)(sm8 + SD_XH + p*ROWB + r*2) = hh;
            *(__half*)(sm8 + SD_XL + p*ROWB + r*2) = ll;
        }
        __syncthreads();

        float g[4][4];
#pragma unroll
        for (int i = 0; i < 4; i++)
#pragma unroll
            for (int j = 0; j < 4; j++) g[i][j] = 0.f;
#pragma unroll
        for (int kk = 0; kk < 4; kk++) {
            uint32_t aH[4], aL4[4];
            uint32_t aoff = (gr0 + (lane & 15)) * ROWB + (kk*16 + (lane >> 4)*8) * 2;
            ldmx4(sb + SD_CH + aoff, aH[0], aH[1], aH[2], aH[3]);
            ldmx4(sb + SD_CL + aoff, aL4[0], aL4[1], aL4[2], aL4[3]);
            uint32_t bH[4][2], bL[4][2];
#pragma unroll
            for (int nt2 = 0; nt2 < 2; nt2++) {
                uint32_t boff = (gc0 + nt2*16 + (lane & 7) + ((lane >> 4) & 1)*8) * ROWB
                              + (kk*16 + ((lane >> 3) & 1)*8) * 2;
                uint32_t r0, r1, r2, r3;
                ldmx4(sb + SD_BH + boff, r0, r1, r2, r3);
                bH[nt2*2][0]=r0; bH[nt2*2][1]=r1; bH[nt2*2+1][0]=r2; bH[nt2*2+1][1]=r3;
                ldmx4(sb + SD_BL + boff, r0, r1, r2, r3);
                bL[nt2*2][0]=r0; bL[nt2*2][1]=r1; bL[nt2*2+1][0]=r2; bL[nt2*2+1][1]=r3;
            }
#pragma unroll
            for (int nt = 0; nt < 4; nt++) {
                mma16816(g[nt], aH,  bH[nt][0], bH[nt][1]);
                mma16816(g[nt], aH,  bL[nt][0], bL[nt][1]);
                mma16816(g[nt], aL4, bH[nt][0], bH[nt][1]);
            }
        }
        {
            int rL = lane >> 2, cc = (lane & 3) * 2;
#pragma unroll
            for (int nt = 0; nt < 4; nt++) {
                int klocal = gc0 + nt*8 + cc;
#pragma unroll
                for (int e = 0; e < 2; e++) {
                    int qrow = gr0 + rL + e*8;
                    int qg = q0 + qrow;
#pragma unroll
                    for (int d = 0; d < 2; d++) {
                        int kg = k0 + klocal + d;
                        float v = 0.f;
                        if (kg <= qg)
                            v = g[nt][e*2 + d] * __expf(acs[qg] - acs[kg]) * dts[kg];
                        __half hh, ll; hsplit(v, hh, ll);
                        *(__half*)(sm8 + SD_GH + qrow*ROWB + (klocal + d)*2) = hh;
                        *(__half*)(sm8 + SD_GL + qrow*ROWB + (klocal + d)*2) = ll;
                    }
                }
            }
        }
        __syncthreads();

#pragma unroll
        for (int kk = 0; kk < 4; kk++) {
            uint32_t aH[4], aL4[4];
            uint32_t aoff = (yr0 + (lane & 15)) * ROWB + (kk*16 + (lane >> 4)*8) * 2;
            ldmx4(sb + SD_GH + aoff, aH[0], aH[1], aH[2], aH[3]);
            ldmx4(sb + SD_GL + aoff, aL4[0], aL4[1], aL4[2], aL4[3]);
            uint32_t bH[8][2], bL[8][2];
#pragma unroll
            for (int nt2 = 0; nt2 < 4; nt2++) {
                uint32_t boff = (yc0 + nt2*16 + (lane & 7) + ((lane >> 4) & 1)*8) * ROWB
                              + (kk*16 + ((lane >> 3) & 1)*8) * 2;
                uint32_t r0, r1, r2, r3;
                ldmx4(sb + SD_XH + boff, r0, r1, r2, r3);
                bH[nt2*2][0]=r0; bH[nt2*2][1]=r1; bH[nt2*2+1][0]=r2; bH[nt2*2+1][1]=r3;
                ldmx4(sb + SD_XL + boff, r0, r1, r2, r3);
                bL[nt2*2][0]=r0; bL[nt2*2][1]=r1; bL[nt2*2+1][0]=r2; bL[nt2*2+1][1]=r3;
            }
#pragma unroll
            for (int nt = 0; nt < 8; nt++) {
                mma16816(accY[nt], aH,  bH[nt][0], bH[nt][1]);
                mma16816(accY[nt], aH,  bL[nt][0], bL[nt][1]);
                mma16816(accY[nt], aL4, bH[nt][0], bH[nt][1]);
            }
        }
    }

    // ---- epilogue: D-skip, gate, fp16 hi/lo triple into g_a3 ----
    float Dh = D_skip[h];
    int rL = lane >> 2, cc = (lane & 3) * 2;
#pragma unroll
    for (int e = 0; e < 2; e++) {
        int m = m0 + q0 + yr0 + rL + e*8;
#pragma unroll
        for (int nt = 0; nt < 8; nt++) {
            int col = h*HD + yc0 + nt*8 + cc;
            float2 xv = *(const float2*)&g_xbc[(size_t)m * CONVDIM + col];
            float2 zz = *(const float2*)&g_proj[(size_t)m * DPROJ + col];
            float y0 = accY[nt][e*2 + 0] + xv.x * Dh;
            float y1 = accY[nt][e*2 + 1] + xv.y * Dh;
            y0 *= zz.x / (1.f + __expf(-zz.x));
            y1 *= zz.y / (1.f + __expf(-zz.y));
            __half h0, l0h, h1, l1h;
            hsplit(y0, h0, l0h); hsplit(y1, h1, l1h);
            __half2 Hh = __halves2half2(h0, h1), Ll = __halves2half2(l0h, l1h);
            __half* basep = g_a3 + (size_t)m * (3*DINNER) + col;
            *(__half2*)(basep)            = Hh;
            *(__half2*)(basep + DINNER)   = Hh;
            *(__half2*)(basep + 2*DINNER) = Ll;
        }
    }
}

// ---------------- launch ----------------
extern "C" void kernel_launch(void* const* d_in, const int* in_sizes, int n_in,
                              void* d_out, int out_size)
{
    const float* x       = (const float*)d_in[0];
    const float* W_in    = (const float*)d_in[1];
    const float* conv_w  = (const float*)d_in[2];
    const float* conv_b  = (const float*)d_in[3];
    const float* A_log   = (const float*)d_in[4];
    const float* dt_bias = (const float*)d_in[5];
    const float* D_skip  = (const float*)d_in[6];
    const float* W_out   = (const float*)d_in[7];
    float* out = (float*)d_out;
    (void)in_sizes; (void)n_in; (void)out_size;

    float *proj = nullptr;
    __half *a3 = nullptr, *b3 = nullptr;
    cudaGetSymbolAddress((void**)&proj, g_proj);
    cudaGetSymbolAddress((void**)&a3, g_a3);
    cudaGetSymbolAddress((void**)&b3, g_b3);

    cudaFuncSetAttribute(k_states, cudaFuncAttributeMaxDynamicSharedMemorySize, ST_SMEM);
    cudaFuncSetAttribute(k_ssdout, cudaFuncAttributeMaxDynamicSharedMemorySize, SD_SMEM);
    cudaFuncSetAttribute(gemm_h3,  cudaFuncAttributeMaxDynamicSharedMemorySize, GSMEM);

    // 1) split-convert inputs, then proj = x @ W_in^T (HMMA)
    k_cvt3<<<(MROWS * (DMODEL/4) + 255)/256, 256>>>((const float4*)x, a3, MROWS, DMODEL, MROWS, 0);
    k_cvt3<<<(NPAD1 * (DMODEL/4) + 255)/256, 256>>>((const float4*)W_in, b3, DPROJ, DMODEL, NPAD1, 1);
    gemm_h3<<<dim3(NPAD1/256, MROWS/128), 256, GSMEM>>>(a3, b3, proj, MROWS, DPROJ, 3*DMODEL);
    // 2) conv + silu
    k_conv<<<dim3(CONVDIM/128, LSEQ/64, BZ), 128>>>(conv_w, conv_b);
    // 3) dt softplus + per-chunk cumsum
    k_dtacs<<<BZ*NCHUNK*NH, 256>>>(dt_bias, A_log);
    // 4) per-chunk states (HMMA)
    k_states<<<BZ*NCHUNK*NH, 256, ST_SMEM>>>();
    // 5) inter-chunk scan
    k_scan<<<BZ*NH, 256>>>();
    // 6) fused SSD output (HMMA) -> fp16 triple (GEMM2 A operand)
    k_ssdout<<<BZ*NCHUNK*NH*4, 256, SD_SMEM>>>(D_skip);
    // 7) convert W_out, then out = y @ W_out^T (HMMA)
    k_cvt3<<<(DMODEL * (DINNER/4) + 255)/256, 256>>>((const float4*)W_out, b3, DMODEL, DINNER, DMODEL, 1);
    gemm_h3<<<dim3(DMODEL/256, MROWS/128), 256, GSMEM>>>(a3, b3, out, MROWS, DMODEL, 3*DINNER);
}

// round 9
// speedup vs baseline: 1.4887x; 1.4887x over previous
#include <cuda_runtime.h>
#include <cuda_fp16.h>
#include <cstdint>
#include <math.h>

// ---------------- problem constants ----------------
#define BZ      2
#define LSEQ    4096
#define DMODEL  1024
#define DINNER  2048
#define NH      16
#define HD      128
#define DS      64
#define CHUNKT  256
#define NCHUNK  16
#define CONVDIM 2176
#define DPROJ   4240          // DINNER + CONVDIM + NH
#define MROWS   (BZ*LSEQ)     // 8192
#define NPAD1   4352          // ceil(4240/128)*128

// ---------------- scratch (device globals; allocation-free) ----------------
__device__ float g_proj[(size_t)MROWS * DPROJ];
__device__ float g_xbc [(size_t)MROWS * CONVDIM];
__device__ float g_dt  [MROWS * NH];
__device__ float g_Acs [BZ * NCHUNK * NH * CHUNKT];
__device__ float g_states[BZ * NCHUNK * NH * HD * DS];
__device__ float g_prevs [BZ * NCHUNK * NH * HD * DS];
__device__ __half g_a3[(size_t)MROWS * 2 * 2048];               // GEMM A, fp16 [Ah|Al]
__device__ __half g_b3[(size_t)NPAD1 * 2048];                   // GEMM B, fp16 [Bh|Bh]

__device__ __forceinline__ uint32_t smem_u32(const void* p) {
    uint32_t a;
    asm("{ .reg .u64 t; cvta.to.shared.u64 t, %1; cvt.u32.u64 %0, t; }" : "=r"(a) : "l"(p));
    return a;
}
__device__ __forceinline__ void cp16(uint32_t dst, const void* src) {
    asm volatile("cp.async.cg.shared.global [%0], [%1], 16;" :: "r"(dst), "l"(src));
}
__device__ __forceinline__ void cp_commit() { asm volatile("cp.async.commit_group;"); }
template<int NN> __device__ __forceinline__ void cp_wait() {
    asm volatile("cp.async.wait_group %0;" :: "n"(NN));
}
__device__ __forceinline__ void ldmx4(uint32_t addr, uint32_t& r0, uint32_t& r1,
                                      uint32_t& r2, uint32_t& r3) {
    asm volatile("ldmatrix.sync.aligned.m8n8.x4.shared.b16 {%0,%1,%2,%3}, [%4];"
        : "=r"(r0), "=r"(r1), "=r"(r2), "=r"(r3) : "r"(addr));
}
__device__ __forceinline__ void mma16816(float* c, const uint32_t* a, uint32_t b0, uint32_t b1) {
    asm volatile("mma.sync.aligned.m16n8k16.row.col.f32.f16.f16.f32 "
        "{%0,%1,%2,%3}, {%4,%5,%6,%7}, {%8,%9}, {%0,%1,%2,%3};"
        : "+f"(c[0]), "+f"(c[1]), "+f"(c[2]), "+f"(c[3])
        : "r"(a[0]), "r"(a[1]), "r"(a[2]), "r"(a[3]), "r"(b0), "r"(b1));
}
__device__ __forceinline__ void hsplit(float v, __half& h, __half& l) {
    h = __float2half_rn(v);
    l = __float2half_rn(v - __half2float(h));
}

#define ROWB 144   // padded smem row stride for 64-half rows (SSD kernels)

// ---------------- fp32 -> fp16, K doubled ----------------
// isB=0 (A side): [Ah | Al]   isB=1 (B side): [Bh | Bh]
__global__ __launch_bounds__(256) void k_cvt2(
    const float4* __restrict__ src, __half* __restrict__ dst,
    int R, int K, int Rpad, int isB)
{
    int kw = K >> 2;
    int idx = blockIdx.x * 256 + threadIdx.x;
    if (idx >= Rpad * kw) return;
    int r = idx / kw, k4 = idx - r * kw;
    float4 v = make_float4(0.f, 0.f, 0.f, 0.f);
    if (r < R) v = src[(size_t)r * kw + k4];
    __half h0, l0h, h1, l1h, h2, l2h, h3, l3h;
    hsplit(v.x, h0, l0h); hsplit(v.y, h1, l1h);
    hsplit(v.z, h2, l2h); hsplit(v.w, h3, l3h);
    __half2 H0 = __halves2half2(h0, h1), H1 = __halves2half2(h2, h3);
    __half2 L0 = __halves2half2(l0h, l1h), L1 = __halves2half2(l2h, l3h);
    size_t base = (size_t)r * 2 * K + 4 * k4;
    __half2* d0 = (__half2*)(dst + base);
    __half2* d1 = (__half2*)(dst + base + K);
    d0[0] = H0; d0[1] = H1;
    if (isB) { d1[0] = H0; d1[1] = H1; }
    else     { d1[0] = L0; d1[1] = L1; }
}

// ---------------- HMMA GEMM (NT): C[M,N] = A[M,K2] * B[N,K2]^T ----------------
// 128x128 CTA tile, BK=32 halves, 4-stage cp.async pipeline, 8 warps of 64x32.
#define GPADB 80
#define GSTGB 20480
#define GSMEM (4 * GSTGB)

__global__ __launch_bounds__(256) void gemm_h3(
    const __half* __restrict__ A, const __half* __restrict__ B,
    float* __restrict__ C, int M, int N, int K3)
{
    extern __shared__ __align__(16) char smem_raw[];
    uint32_t sb = smem_u32(smem_raw);
    const int tid = threadIdx.x;
    const int wid = tid >> 5, lane = tid & 31;
    const int m0 = blockIdx.y * 128, n0 = blockIdx.x * 128;
    const int KT = K3 >> 5;
    const int wm = (wid >> 2) * 64, wn = (wid & 3) * 32;

    const int lrow = tid >> 1;
    const int lseg0 = (tid & 1) * 2;

    float acc[4][4][4];
#pragma unroll
    for (int a = 0; a < 4; a++)
#pragma unroll
        for (int b = 0; b < 4; b++)
#pragma unroll
            for (int c = 0; c < 4; c++) acc[a][b][c] = 0.f;

    auto load_stage = [&](int kt) {
        uint32_t sA = sb + (kt & 3) * GSTGB;
        uint32_t sB = sA + 10240;
        const __half* ga = A + (size_t)(m0 + lrow) * K3 + kt * 32;
        const __half* gb = B + (size_t)(n0 + lrow) * K3 + kt * 32;
#pragma unroll
        for (int s = 0; s < 2; s++) {
            cp16(sA + lrow * GPADB + (lseg0 + s) * 16, ga + (lseg0 + s) * 8);
            cp16(sB + lrow * GPADB + (lseg0 + s) * 16, gb + (lseg0 + s) * 8);
        }
    };

    load_stage(0); cp_commit();
    load_stage(1); cp_commit();
    load_stage(2); cp_commit();

    for (int kt = 0; kt < KT; kt++) {
        cp_wait<2>();
        __syncthreads();
        if (kt + 3 < KT) load_stage(kt + 3);
        cp_commit();
        uint32_t sA = sb + (kt & 3) * GSTGB;
        uint32_t sB = sA + 10240;
#pragma unroll
        for (int kk = 0; kk < 2; kk++) {
            uint32_t a[4][4], b[4][2];
#pragma unroll
            for (int mt = 0; mt < 4; mt++) {
                uint32_t addr = sA + (wm + mt * 16 + (lane & 15)) * GPADB
                              + (kk * 16 + (lane >> 4) * 8) * 2;
                ldmx4(addr, a[mt][0], a[mt][1], a[mt][2], a[mt][3]);
            }
#pragma unroll
            for (int nt2 = 0; nt2 < 2; nt2++) {
                uint32_t r0, r1, r2, r3;
                int n = wn + nt2 * 16 + (lane & 7) + ((lane >> 4) & 1) * 8;
                int kc = kk * 16 + ((lane >> 3) & 1) * 8;
                ldmx4(sB + n * GPADB + kc * 2, r0, r1, r2, r3);
                b[nt2*2][0] = r0; b[nt2*2][1] = r1;
                b[nt2*2+1][0] = r2; b[nt2*2+1][1] = r3;
            }
#pragma unroll
            for (int mt = 0; mt < 4; mt++)
#pragma unroll
                for (int nt = 0; nt < 4; nt++)
                    mma16816(acc[mt][nt], a[mt], b[nt][0], b[nt][1]);
        }
    }

#pragma unroll
    for (int mt = 0; mt < 4; mt++) {
        int r0 = m0 + wm + mt * 16 + (lane >> 2);
#pragma unroll
        for (int nt = 0; nt < 4; nt++) {
            int cb = n0 + wn + nt * 8 + (lane & 3) * 2;
            if (cb < N) {
                *(float2*)(C + (size_t)r0 * N + cb) =
                    make_float2(acc[mt][nt][0], acc[mt][nt][1]);
                *(float2*)(C + (size_t)(r0 + 8) * N + cb) =
                    make_float2(acc[mt][nt][2], acc[mt][nt][3]);
            }
        }
    }
}

// ---------------- depthwise causal conv (D_CONV=4) + bias + SiLU ----------------
__global__ __launch_bounds__(128) void k_conv(
    const float* __restrict__ cw, const float* __restrict__ cb)
{
    int c = blockIdx.x * 128 + threadIdx.x;
    int b = blockIdx.z;
    int l0 = blockIdx.y * 64;
    float w0 = cw[c*4+0], w1 = cw[c*4+1], w2 = cw[c*4+2], w3 = cw[c*4+3];
    float bias = cb[c];
    const float* pp = g_proj + (size_t)b * LSEQ * DPROJ + DINNER + c;
    float* op = g_xbc + (size_t)b * LSEQ * CONVDIM + c;
    float xm3 = 0.f, xm2 = 0.f, xm1 = 0.f;
    if (l0 >= 3) {
        xm3 = pp[(size_t)(l0-3) * DPROJ];
        xm2 = pp[(size_t)(l0-2) * DPROJ];
        xm1 = pp[(size_t)(l0-1) * DPROJ];
    }
#pragma unroll 4
    for (int i = 0; i < 64; i++) {
        int l = l0 + i;
        float xc = pp[(size_t)l * DPROJ];
        float s = w3*xc + w2*xm1 + w1*xm2 + w0*xm3 + bias;
        float sig = 1.f / (1.f + expf(-s));
        op[(size_t)l * CONVDIM] = s * sig;
        xm3 = xm2; xm2 = xm1; xm1 = xc;
    }
}

// ---------------- dt = softplus(...) fused with per-chunk cumsum of dt*A ----------------
__global__ __launch_bounds__(256) void k_dtacs(
    const float* __restrict__ dt_bias, const float* __restrict__ A_log)
{
    int blk = blockIdx.x;
    int h = blk & 15, c = (blk >> 4) & 15, b = blk >> 8;
    int t = threadIdx.x;
    int m = b * LSEQ + c * CHUNKT + t;
    float v = g_proj[(size_t)m * DPROJ + (DINNER + CONVDIM) + h] + dt_bias[h];
    float dt = (v > 20.f) ? v : log1pf(expf(v));
    g_dt[m * NH + h] = dt;
    float A = -expf(A_log[h]);
    __shared__ float s[CHUNKT];
    s[t] = dt * A;
    __syncthreads();
    for (int off = 1; off < CHUNKT; off <<= 1) {
        float u = (t >= off) ? s[t - off] : 0.f;
        __syncthreads();
        s[t] += u;
        __syncthreads();
    }
    g_Acs[blk * CHUNKT + t] = s[t];
}

// ---------------- per-chunk states (HMMA): S[p,n] = sum_k x[k,p]*w[k]*B[k,n] ----------------
#define ST_XH 0
#define ST_XL 18432
#define ST_BH 36864
#define ST_BL 46080
#define ST_SC 55296
#define ST_SMEM 56320

__global__ __launch_bounds__(256) void k_states()
{
    extern __shared__ __align__(16) char sm9[];
    const uint32_t sb = smem_u32(sm9);
    float* sc = (float*)(sm9 + ST_SC);
    int blk = blockIdx.x;
    int h = blk & 15, c = (blk >> 4) & 15, b = blk >> 8;
    int t = threadIdx.x;
    int wid = t >> 5, lane = t & 31;
    int m0 = b * LSEQ + c * CHUNKT;
    float aL = g_Acs[blk * CHUNKT + 255];
    sc[t] = g_dt[(m0 + t) * NH + h] * __expf(aL - g_Acs[blk * CHUNKT + t]);

    const int pr0 = wid * 16;
    float acc[8][4];
#pragma unroll
    for (int i = 0; i < 8; i++)
#pragma unroll
        for (int j = 0; j < 4; j++) acc[i][j] = 0.f;

    for (int kt = 0; kt < 4; kt++) {
        int k0 = kt * 64;
        __syncthreads();
        for (int i = t; i < 64*128; i += 256) {
            int r = i >> 7, p = i & 127;
            float v = g_xbc[(size_t)(m0 + k0 + r) * CONVDIM + h*HD + p];
            __half hh, ll; hsplit(v, hh, ll);
            *(__half*)(sm9 + ST_XH + p*ROWB + r*2) = hh;
            *(__half*)(sm9 + ST_XL + p*ROWB + r*2) = ll;
        }
        for (int i = t; i < 64*64; i += 256) {
            int r = i >> 6, n = i & 63;
            float v = g_xbc[(size_t)(m0 + k0 + r) * CONVDIM + DINNER + n] * sc[k0 + r];
            __half hh, ll; hsplit(v, hh, ll);
            *(__half*)(sm9 + ST_BH + n*ROWB + r*2) = hh;
            *(__half*)(sm9 + ST_BL + n*ROWB + r*2) = ll;
        }
        __syncthreads();
#pragma unroll
        for (int kk = 0; kk < 4; kk++) {
            uint32_t aH[4], aL4[4];
            uint32_t aoff = (pr0 + (lane & 15)) * ROWB + (kk*16 + (lane >> 4)*8) * 2;
            ldmx4(sb + ST_XH + aoff, aH[0], aH[1], aH[2], aH[3]);
            ldmx4(sb + ST_XL + aoff, aL4[0], aL4[1], aL4[2], aL4[3]);
            uint32_t bH[8][2], bL[8][2];
#pragma unroll
            for (int nt2 = 0; nt2 < 4; nt2++) {
                uint32_t boff = (nt2*16 + (lane & 7) + ((lane >> 4) & 1)*8) * ROWB
                              + (kk*16 + ((lane >> 3) & 1)*8) * 2;
                uint32_t r0, r1, r2, r3;
                ldmx4(sb + ST_BH + boff, r0, r1, r2, r3);
                bH[nt2*2][0]=r0; bH[nt2*2][1]=r1; bH[nt2*2+1][0]=r2; bH[nt2*2+1][1]=r3;
                ldmx4(sb + ST_BL + boff, r0, r1, r2, r3);
                bL[nt2*2][0]=r0; bL[nt2*2][1]=r1; bL[nt2*2+1][0]=r2; bL[nt2*2+1][1]=r3;
            }
#pragma unroll
            for (int nt = 0; nt < 8; nt++) {
                mma16816(acc[nt], aH,  bH[nt][0], bH[nt][1]);
                mma16816(acc[nt], aH,  bL[nt][0], bL[nt][1]);
                mma16816(acc[nt], aL4, bH[nt][0], bH[nt][1]);
            }
        }
    }
    int base = blk * HD * DS;
    int rL = lane >> 2, cc = (lane & 3) * 2;
#pragma unroll
    for (int e = 0; e < 2; e++) {
        int p = pr0 + rL + e*8;
#pragma unroll
        for (int nt = 0; nt < 8; nt++) {
            int n = nt*8 + cc;
            *(float2*)&g_states[base + p*DS + n] =
                make_float2(acc[nt][e*2], acc[nt][e*2+1]);
        }
    }
}

// ---------------- inter-chunk sequential scan ----------------
__global__ __launch_bounds__(256) void k_scan()
{
    int b = blockIdx.x >> 4, h = blockIdx.x & 15;
    int t = threadIdx.x;
    float prev[32];
#pragma unroll
    for (int j = 0; j < 32; j++) prev[j] = 0.f;
    for (int c = 0; c < NCHUNK; c++) {
        int bch = (b * NCHUNK + c) * NH + h;
        int base = bch * HD * DS;
#pragma unroll
        for (int j = 0; j < 32; j++) g_prevs[base + j*256 + t] = prev[j];
        float e = __expf(g_Acs[bch * CHUNKT + 255]);
#pragma unroll
        for (int j = 0; j < 32; j++)
            prev[j] = e * prev[j] + g_states[base + j*256 + t];
    }
}

// ---------------- fused HMMA: Y_diag + Y_off + D-skip + gate -> fp16 [Ah|Al] ----------------
#define SD_CH  0
#define SD_CL  9216
#define SD_BH  18432
#define SD_BL  27648
#define SD_XH  36864
#define SD_XL  55296
#define SD_GH  73728
#define SD_GL  82944
#define SD_ACS 92160
#define SD_DTS 93184
#define SD_SMEM 94208
// Pv (128x64) overlays XH/XL; consumed in phase1 before k-tile staging overwrites them.

__global__ __launch_bounds__(256) void k_ssdout(const float* __restrict__ D_skip)
{
    extern __shared__ __align__(16) char sm8[];
    const uint32_t sb = smem_u32(sm8);
    float* acs = (float*)(sm8 + SD_ACS);
    float* dts = (float*)(sm8 + SD_DTS);

    int blk = blockIdx.x;             // 2048
    int qb = blk & 3;
    int bch = blk >> 2;
    int h = bch & 15, c = (bch >> 4) & 15, b = bch >> 8;
    int t = threadIdx.x;
    int wid = t >> 5, lane = t & 31;
    int m0 = b * LSEQ + c * CHUNKT;
    int q0 = qb * 64;

    acs[t] = g_Acs[bch * CHUNKT + t];
    dts[t] = g_dt[(m0 + t) * NH + h];
    for (int i = t; i < 64*64; i += 256) {
        int q = i >> 6, n = i & 63;
        float v = g_xbc[(size_t)(m0 + q0 + q) * CONVDIM + (DINNER + DS) + n];
        __half hh, ll; hsplit(v, hh, ll);
        *(__half*)(sm8 + SD_CH + q*ROWB + n*2) = hh;
        *(__half*)(sm8 + SD_CL + q*ROWB + n*2) = ll;
    }
    for (int i = t; i < 128*64; i += 256) {
        int p = i >> 6, n = i & 63;
        float v = g_prevs[bch * HD * DS + p*DS + n];
        __half hh, ll; hsplit(v, hh, ll);
        *(__half*)(sm8 + SD_XH + p*ROWB + n*2) = hh;
        *(__half*)(sm8 + SD_XL + p*ROWB + n*2) = ll;
    }
    __syncthreads();

    const int yr0 = (wid >> 1) * 16;
    const int yc0 = (wid & 1) * 64;
    float accY[8][4];
#pragma unroll
    for (int i = 0; i < 8; i++)
#pragma unroll
        for (int j = 0; j < 4; j++) accY[i][j] = 0.f;

    // ---- phase 1: Y = C @ Pv^T ----
#pragma unroll
    for (int kk = 0; kk < 4; kk++) {
        uint32_t aH[4], aL4[4];
        uint32_t aoff = (yr0 + (lane & 15)) * ROWB + (kk*16 + (lane >> 4)*8) * 2;
        ldmx4(sb + SD_CH + aoff, aH[0], aH[1], aH[2], aH[3]);
        ldmx4(sb + SD_CL + aoff, aL4[0], aL4[1], aL4[2], aL4[3]);
        uint32_t bH[8][2], bL[8][2];
#pragma unroll
        for (int nt2 = 0; nt2 < 4; nt2++) {
            uint32_t boff = (yc0 + nt2*16 + (lane & 7) + ((lane >> 4) & 1)*8) * ROWB
                          + (kk*16 + ((lane >> 3) & 1)*8) * 2;
            uint32_t r0, r1, r2, r3;
            ldmx4(sb + SD_XH + boff, r0, r1, r2, r3);
            bH[nt2*2][0]=r0; bH[nt2*2][1]=r1; bH[nt2*2+1][0]=r2; bH[nt2*2+1][1]=r3;
            ldmx4(sb + SD_XL + boff, r0, r1, r2, r3);
            bL[nt2*2][0]=r0; bL[nt2*2][1]=r1; bL[nt2*2+1][0]=r2; bL[nt2*2+1][1]=r3;
        }
#pragma unroll
        for (int nt = 0; nt < 8; nt++) {
            mma16816(accY[nt], aH,  bH[nt][0], bH[nt][1]);
            mma16816(accY[nt], aH,  bL[nt][0], bL[nt][1]);
            mma16816(accY[nt], aL4, bH[nt][0], bH[nt][1]);
        }
    }
    {
        float e0 = __expf(acs[q0 + yr0 + (lane >> 2)]);
        float e1 = __expf(acs[q0 + yr0 + (lane >> 2) + 8]);
#pragma unroll
        for (int nt = 0; nt < 8; nt++) {
            accY[nt][0] *= e0; accY[nt][1] *= e0;
            accY[nt][2] *= e1; accY[nt][3] *= e1;
        }
    }

    // ---- phase 2: Y_diag over k-tiles ----
    const int gr0 = yr0, gc0 = (wid & 1) * 32;
    for (int kt = 0; kt <= qb; kt++) {
        int k0 = kt * 64;
        __syncthreads();
        for (int i = t; i < 64*64; i += 256) {
            int r = i >> 6, n = i & 63;
            float v = g_xbc[(size_t)(m0 + k0 + r) * CONVDIM + DINNER + n];
            __half hh, ll; hsplit(v, hh, ll);
            *(__half*)(sm8 + SD_BH + r*ROWB + n*2) = hh;
            *(__half*)(sm8 + SD_BL + r*ROWB + n*2) = ll;
        }
        for (int i = t; i < 64*128; i += 256) {
            int r = i >> 7, p = i & 127;
            float v = g_xbc[(size_t)(m0 + k0 + r) * CONVDIM + h*HD + p];
            __half hh, ll; hsplit(v, hh, ll);
            *(__half*)(sm8 + SD_XH + p*ROWB + r*2) = hh;
            *(__half*)(sm8 + SD_XL + p*ROWB + r*2) = ll;
        }
        __syncthreads();

        float g[4][4];
#pragma unroll
        for (int i = 0; i < 4; i++)
#pragma unroll
            for (int j = 0; j < 4; j++) g[i][j] = 0.f;
#pragma unroll
        for (int kk = 0; kk < 4; kk++) {
            uint32_t aH[4], aL4[4];
            uint32_t aoff = (gr0 + (lane & 15)) * ROWB + (kk*16 + (lane >> 4)*8) * 2;
            ldmx4(sb + SD_CH + aoff, aH[0], aH[1], aH[2], aH[3]);
            ldmx4(sb + SD_CL + aoff, aL4[0], aL4[1], aL4[2], aL4[3]);
            uint32_t bH[4][2], bL[4][2];
#pragma unroll
            for (int nt2 = 0; nt2 < 2; nt2++) {
                uint32_t boff = (gc0 + nt2*16 + (lane & 7) + ((lane >> 4) & 1)*8) * ROWB
                              + (kk*16 + ((lane >> 3) & 1)*8) * 2;
                uint32_t r0, r1, r2, r3;
                ldmx4(sb + SD_BH + boff, r0, r1, r2, r3);
                bH[nt2*2][0]=r0; bH[nt2*2][1]=r1; bH[nt2*2+1][0]=r2; bH[nt2*2+1][1]=r3;
                ldmx4(sb + SD_BL + boff, r0, r1, r2, r3);
                bL[nt2*2][0]=r0; bL[nt2*2][1]=r1; bL[nt2*2+1][0]=r2; bL[nt2*2+1][1]=r3;
            }
#pragma unroll
            for (int nt = 0; nt < 4; nt++) {
                mma16816(g[nt], aH,  bH[nt][0], bH[nt][1]);
                mma16816(g[nt], aH,  bL[nt][0], bL[nt][1]);
                mma16816(g[nt], aL4, bH[nt][0], bH[nt][1]);
            }
        }
        {
            int rL = lane >> 2, cc = (lane & 3) * 2;
#pragma unroll
            for (int nt = 0; nt < 4; nt++) {
                int klocal = gc0 + nt*8 + cc;
#pragma unroll
                for (int e = 0; e < 2; e++) {
                    int qrow = gr0 + rL + e*8;
                    int qg = q0 + qrow;
#pragma unroll
                    for (int d = 0; d < 2; d++) {
                        int kg = k0 + klocal + d;
                        float v = 0.f;
                        if (kg <= qg)
                            v = g[nt][e*2 + d] * __expf(acs[qg] - acs[kg]) * dts[kg];
                        __half hh, ll; hsplit(v, hh, ll);
                        *(__half*)(sm8 + SD_GH + qrow*ROWB + (klocal + d)*2) = hh;
                        *(__half*)(sm8 + SD_GL + qrow*ROWB + (klocal + d)*2) = ll;
                    }
                }
            }
        }
        __syncthreads();

#pragma unroll
        for (int kk = 0; kk < 4; kk++) {
            uint32_t aH[4], aL4[4];
            uint32_t aoff = (yr0 + (lane & 15)) * ROWB + (kk*16 + (lane >> 4)*8) * 2;
            ldmx4(sb + SD_GH + aoff, aH[0], aH[1], aH[2], aH[3]);
            ldmx4(sb + SD_GL + aoff, aL4[0], aL4[1], aL4[2], aL4[3]);
            uint32_t bH[8][2], bL[8][2];
#pragma unroll
            for (int nt2 = 0; nt2 < 4; nt2++) {
                uint32_t boff = (yc0 + nt2*16 + (lane & 7) + ((lane >> 4) & 1)*8) * ROWB
                              + (kk*16 + ((lane >> 3) & 1)*8) * 2;
                uint32_t r0, r1, r2, r3;
                ldmx4(sb + SD_XH + boff, r0, r1, r2, r3);
                bH[nt2*2][0]=r0; bH[nt2*2][1]=r1; bH[nt2*2+1][0]=r2; bH[nt2*2+1][1]=r3;
                ldmx4(sb + SD_XL + boff, r0, r1, r2, r3);
                bL[nt2*2][0]=r0; bL[nt2*2][1]=r1; bL[nt2*2+1][0]=r2; bL[nt2*2+1][1]=r3;
            }
#pragma unroll
            for (int nt = 0; nt < 8; nt++) {
                mma16816(accY[nt], aH,  bH[nt][0], bH[nt][1]);
                mma16816(accY[nt], aH,  bL[nt][0], bL[nt][1]);
                mma16816(accY[nt], aL4, bH[nt][0], bH[nt][1]);
            }
        }
    }

    // ---- epilogue: D-skip, gate, fp16 [Ah|Al] into g_a3 ----
    float Dh = D_skip[h];
    int rL = lane >> 2, cc = (lane & 3) * 2;
#pragma unroll
    for (int e = 0; e < 2; e++) {
        int m = m0 + q0 + yr0 + rL + e*8;
#pragma unroll
        for (int nt = 0; nt < 8; nt++) {
            int col = h*HD + yc0 + nt*8 + cc;
            float2 xv = *(const float2*)&g_xbc[(size_t)m * CONVDIM + col];
            float2 zz = *(const float2*)&g_proj[(size_t)m * DPROJ + col];
            float y0 = accY[nt][e*2 + 0] + xv.x * Dh;
            float y1 = accY[nt][e*2 + 1] + xv.y * Dh;
            y0 *= zz.x / (1.f + __expf(-zz.x));
            y1 *= zz.y / (1.f + __expf(-zz.y));
            __half h0, l0h, h1, l1h;
            hsplit(y0, h0, l0h); hsplit(y1, h1, l1h);
            __half2 Hh = __halves2half2(h0, h1), Ll = __halves2half2(l0h, l1h);
            __half* basep = g_a3 + (size_t)m * (2*DINNER) + col;
            *(__half2*)(basep)          = Hh;
            *(__half2*)(basep + DINNER) = Ll;
        }
    }
}

// ---------------- launch ----------------
extern "C" void kernel_launch(void* const* d_in, const int* in_sizes, int n_in,
                              void* d_out, int out_size)
{
    const float* x       = (const float*)d_in[0];
    const float* W_in    = (const float*)d_in[1];
    const float* conv_w  = (const float*)d_in[2];
    const float* conv_b  = (const float*)d_in[3];
    const float* A_log   = (const float*)d_in[4];
    const float* dt_bias = (const float*)d_in[5];
    const float* D_skip  = (const float*)d_in[6];
    const float* W_out   = (const float*)d_in[7];
    float* out = (float*)d_out;
    (void)in_sizes; (void)n_in; (void)out_size;

    float *proj = nullptr;
    __half *a3 = nullptr, *b3 = nullptr;
    cudaGetSymbolAddress((void**)&proj, g_proj);
    cudaGetSymbolAddress((void**)&a3, g_a3);
    cudaGetSymbolAddress((void**)&b3, g_b3);

    cudaFuncSetAttribute(k_states, cudaFuncAttributeMaxDynamicSharedMemorySize, ST_SMEM);
    cudaFuncSetAttribute(k_ssdout, cudaFuncAttributeMaxDynamicSharedMemorySize, SD_SMEM);
    cudaFuncSetAttribute(gemm_h3,  cudaFuncAttributeMaxDynamicSharedMemorySize, GSMEM);

    // 1) convert inputs (2-product split), then proj = x @ W_in^T (HMMA)
    k_cvt2<<<(MROWS * (DMODEL/4) + 255)/256, 256>>>((const float4*)x, a3, MROWS, DMODEL, MROWS, 0);
    k_cvt2<<<(NPAD1 * (DMODEL/4) + 255)/256, 256>>>((const float4*)W_in, b3, DPROJ, DMODEL, NPAD1, 1);
    gemm_h3<<<dim3(NPAD1/128, MROWS/128), 256, GSMEM>>>(a3, b3, proj, MROWS, DPROJ, 2*DMODEL);
    // 2) conv + silu
    k_conv<<<dim3(CONVDIM/128, LSEQ/64, BZ), 128>>>(conv_w, conv_b);
    // 3) dt softplus + per-chunk cumsum
    k_dtacs<<<BZ*NCHUNK*NH, 256>>>(dt_bias, A_log);
    // 4) per-chunk states (HMMA, 3-product)
    k_states<<<BZ*NCHUNK*NH, 256, ST_SMEM>>>();
    // 5) inter-chunk scan
    k_scan<<<BZ*NH, 256>>>();
    // 6) fused SSD output (HMMA, 3-product) -> fp16 [Ah|Al] (GEMM2 A operand)
    k_ssdout<<<BZ*NCHUNK*NH*4, 256, SD_SMEM>>>(D_skip);
    // 7) convert W_out, then out = y @ W_out^T (HMMA)
    k_cvt2<<<(DMODEL * (DINNER/4) + 255)/256, 256>>>((const float4*)W_out, b3, DMODEL, DINNER, DMODEL, 1);
    gemm_h3<<<dim3(DMODEL/128, MROWS/128), 256, GSMEM>>>(a3, b3, out, MROWS, DMODEL, 2*DINNER);
}

// round 10
// speedup vs baseline: 1.5923x; 1.0696x over previous
#include <cuda_runtime.h>
#include <cuda_fp16.h>
#include <cstdint>
#include <math.h>

// ---------------- problem constants ----------------
#define BZ      2
#define LSEQ    4096
#define DMODEL  1024
#define DINNER  2048
#define NH      16
#define HD      128
#define DS      64
#define CHUNKT  256
#define NCHUNK  16
#define CONVDIM 2176
#define DPROJ   4240          // DINNER + CONVDIM + NH
#define MROWS   (BZ*LSEQ)     // 8192
#define NPAD1   4352          // ceil(4240/256)*256

// ---------------- scratch (device globals; allocation-free) ----------------
__device__ float g_proj[(size_t)MROWS * DPROJ];
__device__ float g_xbc [(size_t)MROWS * CONVDIM];
__device__ float g_dt  [MROWS * NH];
__device__ float g_Acs [BZ * NCHUNK * NH * CHUNKT];
__device__ float g_states[BZ * NCHUNK * NH * HD * DS];
__device__ float g_prevs [BZ * NCHUNK * NH * HD * DS];
__device__ __half g_a3[(size_t)MROWS * 2 * 2048];               // GEMM A, fp16 [Ah|Al]
__device__ __half g_b3[(size_t)NPAD1 * 2048];                   // GEMM B, fp16 [Bh|Bh]

__device__ __forceinline__ uint32_t smem_u32(const void* p) {
    uint32_t a;
    asm("{ .reg .u64 t; cvta.to.shared.u64 t, %1; cvt.u32.u64 %0, t; }" : "=r"(a) : "l"(p));
    return a;
}
__device__ __forceinline__ void cp16(uint32_t dst, const void* src) {
    asm volatile("cp.async.cg.shared.global [%0], [%1], 16;" :: "r"(dst), "l"(src));
}
__device__ __forceinline__ void cp_commit() { asm volatile("cp.async.commit_group;"); }
template<int NN> __device__ __forceinline__ void cp_wait() {
    asm volatile("cp.async.wait_group %0;" :: "n"(NN));
}
__device__ __forceinline__ void ldmx4(uint32_t addr, uint32_t& r0, uint32_t& r1,
                                      uint32_t& r2, uint32_t& r3) {
    asm volatile("ldmatrix.sync.aligned.m8n8.x4.shared.b16 {%0,%1,%2,%3}, [%4];"
        : "=r"(r0), "=r"(r1), "=r"(r2), "=r"(r3) : "r"(addr));
}
__device__ __forceinline__ void mma16816(float* c, const uint32_t* a, uint32_t b0, uint32_t b1) {
    asm volatile("mma.sync.aligned.m16n8k16.row.col.f32.f16.f16.f32 "
        "{%0,%1,%2,%3}, {%4,%5,%6,%7}, {%8,%9}, {%0,%1,%2,%3};"
        : "+f"(c[0]), "+f"(c[1]), "+f"(c[2]), "+f"(c[3])
        : "r"(a[0]), "r"(a[1]), "r"(a[2]), "r"(a[3]), "r"(b0), "r"(b1));
}
__device__ __forceinline__ void hsplit(float v, __half& h, __half& l) {
    h = __float2half_rn(v);
    l = __float2half_rn(v - __half2float(h));
}

#define ROWB 144   // padded smem row stride for 64-half rows (SSD kernels)

// ---------------- fp32 -> fp16, K doubled ----------------
// isB=0 (A side): [Ah | Al]   isB=1 (B side): [Bh | Bh]
__global__ __launch_bounds__(256) void k_cvt2(
    const float4* __restrict__ src, __half* __restrict__ dst,
    int R, int K, int Rpad, int isB)
{
    int kw = K >> 2;
    int idx = blockIdx.x * 256 + threadIdx.x;
    if (idx >= Rpad * kw) return;
    int r = idx / kw, k4 = idx - r * kw;
    float4 v = make_float4(0.f, 0.f, 0.f, 0.f);
    if (r < R) v = src[(size_t)r * kw + k4];
    __half h0, l0h, h1, l1h, h2, l2h, h3, l3h;
    hsplit(v.x, h0, l0h); hsplit(v.y, h1, l1h);
    hsplit(v.z, h2, l2h); hsplit(v.w, h3, l3h);
    __half2 H0 = __halves2half2(h0, h1), H1 = __halves2half2(h2, h3);
    __half2 L0 = __halves2half2(l0h, l1h), L1 = __halves2half2(l2h, l3h);
    size_t base = (size_t)r * 2 * K + 4 * k4;
    __half2* d0 = (__half2*)(dst + base);
    __half2* d1 = (__half2*)(dst + base + K);
    d0[0] = H0; d0[1] = H1;
    if (isB) { d1[0] = H0; d1[1] = H1; }
    else     { d1[0] = L0; d1[1] = L1; }
}

// ---------------- HMMA GEMM (NT): C[M,N] = A[M,K2] * B[N,K2]^T ----------------
// 128(M) x 256(N) CTA tile, 512 threads (16 warps of 64x32), BK=32 halves,
// 4-stage cp.async pipeline.
#define GPADB 80                         // bytes per smem row (40 halves)
#define GSTGA 10240                      // A stage: 128 rows * 80B
#define GSTGB2 20480                     // B stage: 256 rows * 80B
#define GSTG  (GSTGA + GSTGB2)           // 30720 per stage
#define GSMEM (4 * GSTG)                 // 122880

__global__ __launch_bounds__(512) void gemm_h3(
    const __half* __restrict__ A, const __half* __restrict__ B,
    float* __restrict__ C, int M, int N, int K3)
{
    extern __shared__ __align__(16) char smem_raw[];
    uint32_t sb = smem_u32(smem_raw);
    const int tid = threadIdx.x;
    const int wid = tid >> 5, lane = tid & 31;
    const int m0 = blockIdx.y * 128, n0 = blockIdx.x * 256;
    const int KT = K3 >> 5;
    const int wm = (wid >> 3) * 64, wn = (wid & 7) * 32;

    const int arow = tid >> 2;                 // 0..127 (A rows), 1 seg each
    const int aseg = tid & 3;
    const int brow = tid >> 1;                 // 0..255 (B rows), 2 segs each
    const int bseg0 = (tid & 1) * 2;

    float acc[4][4][4];
#pragma unroll
    for (int a = 0; a < 4; a++)
#pragma unroll
        for (int b = 0; b < 4; b++)
#pragma unroll
            for (int c = 0; c < 4; c++) acc[a][b][c] = 0.f;

    auto load_stage = [&](int kt) {
        uint32_t sA = sb + (kt & 3) * GSTG;
        uint32_t sB = sA + GSTGA;
        const __half* ga = A + (size_t)(m0 + arow) * K3 + kt * 32;
        const __half* gb = B + (size_t)(n0 + brow) * K3 + kt * 32;
        cp16(sA + arow * GPADB + aseg * 16, ga + aseg * 8);
#pragma unroll
        for (int s = 0; s < 2; s++)
            cp16(sB + brow * GPADB + (bseg0 + s) * 16, gb + (bseg0 + s) * 8);
    };

    load_stage(0); cp_commit();
    load_stage(1); cp_commit();
    load_stage(2); cp_commit();

    for (int kt = 0; kt < KT; kt++) {
        cp_wait<2>();
        __syncthreads();
        if (kt + 3 < KT) load_stage(kt + 3);
        cp_commit();
        uint32_t sA = sb + (kt & 3) * GSTG;
        uint32_t sB = sA + GSTGA;
#pragma unroll
        for (int kk = 0; kk < 2; kk++) {
            uint32_t a[4][4], b[4][2];
#pragma unroll
            for (int mt = 0; mt < 4; mt++) {
                uint32_t addr = sA + (wm + mt * 16 + (lane & 15)) * GPADB
                              + (kk * 16 + (lane >> 4) * 8) * 2;
                ldmx4(addr, a[mt][0], a[mt][1], a[mt][2], a[mt][3]);
            }
#pragma unroll
            for (int nt2 = 0; nt2 < 2; nt2++) {
                uint32_t r0, r1, r2, r3;
                int n = wn + nt2 * 16 + (lane & 7) + ((lane >> 4) & 1) * 8;
                int kc = kk * 16 + ((lane >> 3) & 1) * 8;
                ldmx4(sB + n * GPADB + kc * 2, r0, r1, r2, r3);
                b[nt2*2][0] = r0; b[nt2*2][1] = r1;
                b[nt2*2+1][0] = r2; b[nt2*2+1][1] = r3;
            }
#pragma unroll
            for (int mt = 0; mt < 4; mt++)
#pragma unroll
                for (int nt = 0; nt < 4; nt++)
                    mma16816(acc[mt][nt], a[mt], b[nt][0], b[nt][1]);
        }
    }

#pragma unroll
    for (int mt = 0; mt < 4; mt++) {
        int r0 = m0 + wm + mt * 16 + (lane >> 2);
#pragma unroll
        for (int nt = 0; nt < 4; nt++) {
            int cb = n0 + wn + nt * 8 + (lane & 3) * 2;
            if (cb < N) {
                *(float2*)(C + (size_t)r0 * N + cb) =
                    make_float2(acc[mt][nt][0], acc[mt][nt][1]);
                *(float2*)(C + (size_t)(r0 + 8) * N + cb) =
                    make_float2(acc[mt][nt][2], acc[mt][nt][3]);
            }
        }
    }
}

// ---------------- depthwise causal conv (D_CONV=4) + bias + SiLU ----------------
__global__ __launch_bounds__(128) void k_conv(
    const float* __restrict__ cw, const float* __restrict__ cb)
{
    int c = blockIdx.x * 128 + threadIdx.x;
    int b = blockIdx.z;
    int l0 = blockIdx.y * 64;
    float w0 = cw[c*4+0], w1 = cw[c*4+1], w2 = cw[c*4+2], w3 = cw[c*4+3];
    float bias = cb[c];
    const float* pp = g_proj + (size_t)b * LSEQ * DPROJ + DINNER + c;
    float* op = g_xbc + (size_t)b * LSEQ * CONVDIM + c;
    float xm3 = 0.f, xm2 = 0.f, xm1 = 0.f;
    if (l0 >= 3) {
        xm3 = pp[(size_t)(l0-3) * DPROJ];
        xm2 = pp[(size_t)(l0-2) * DPROJ];
        xm1 = pp[(size_t)(l0-1) * DPROJ];
    }
#pragma unroll 4
    for (int i = 0; i < 64; i++) {
        int l = l0 + i;
        float xc = pp[(size_t)l * DPROJ];
        float s = w3*xc + w2*xm1 + w1*xm2 + w0*xm3 + bias;
        float sig = 1.f / (1.f + expf(-s));
        op[(size_t)l * CONVDIM] = s * sig;
        xm3 = xm2; xm2 = xm1; xm1 = xc;
    }
}

// ---------------- dt = softplus(...) fused with per-chunk cumsum of dt*A ----------------
__global__ __launch_bounds__(256) void k_dtacs(
    const float* __restrict__ dt_bias, const float* __restrict__ A_log)
{
    int blk = blockIdx.x;
    int h = blk & 15, c = (blk >> 4) & 15, b = blk >> 8;
    int t = threadIdx.x;
    int m = b * LSEQ + c * CHUNKT + t;
    float v = g_proj[(size_t)m * DPROJ + (DINNER + CONVDIM) + h] + dt_bias[h];
    float dt = (v > 20.f) ? v : log1pf(expf(v));
    g_dt[m * NH + h] = dt;
    float A = -expf(A_log[h]);
    __shared__ float s[CHUNKT];
    s[t] = dt * A;
    __syncthreads();
    for (int off = 1; off < CHUNKT; off <<= 1) {
        float u = (t >= off) ? s[t - off] : 0.f;
        __syncthreads();
        s[t] += u;
        __syncthreads();
    }
    g_Acs[blk * CHUNKT + t] = s[t];
}

// ---------------- per-chunk states (HMMA): S[p,n] = sum_k x[k,p]*w[k]*B[k,n] ----------------
#define ST_XH 0
#define ST_XL 18432
#define ST_BH 36864
#define ST_BL 46080
#define ST_SC 55296
#define ST_SMEM 56320

__global__ __launch_bounds__(256) void k_states()
{
    extern __shared__ __align__(16) char sm9[];
    const uint32_t sb = smem_u32(sm9);
    float* sc = (float*)(sm9 + ST_SC);
    int blk = blockIdx.x;
    int h = blk & 15, c = (blk >> 4) & 15, b = blk >> 8;
    int t = threadIdx.x;
    int wid = t >> 5, lane = t & 31;
    int m0 = b * LSEQ + c * CHUNKT;
    float aL = g_Acs[blk * CHUNKT + 255];
    sc[t] = g_dt[(m0 + t) * NH + h] * __expf(aL - g_Acs[blk * CHUNKT + t]);

    const int pr0 = wid * 16;
    float acc[8][4];
#pragma unroll
    for (int i = 0; i < 8; i++)
#pragma unroll
        for (int j = 0; j < 4; j++) acc[i][j] = 0.f;

    for (int kt = 0; kt < 4; kt++) {
        int k0 = kt * 64;
        __syncthreads();
        for (int i = t; i < 64*128; i += 256) {
            int r = i >> 7, p = i & 127;
            float v = g_xbc[(size_t)(m0 + k0 + r) * CONVDIM + h*HD + p];
            __half hh, ll; hsplit(v, hh, ll);
            *(__half*)(sm9 + ST_XH + p*ROWB + r*2) = hh;
            *(__half*)(sm9 + ST_XL + p*ROWB + r*2) = ll;
        }
        for (int i = t; i < 64*64; i += 256) {
            int r = i >> 6, n = i & 63;
            float v = g_xbc[(size_t)(m0 + k0 + r) * CONVDIM + DINNER + n] * sc[k0 + r];
            __half hh, ll; hsplit(v, hh, ll);
            *(__half*)(sm9 + ST_BH + n*ROWB + r*2) = hh;
            *(__half*)(sm9 + ST_BL + n*ROWB + r*2) = ll;
        }
        __syncthreads();
#pragma unroll
        for (int kk = 0; kk < 4; kk++) {
            uint32_t aH[4], aL4[4];
            uint32_t aoff = (pr0 + (lane & 15)) * ROWB + (kk*16 + (lane >> 4)*8) * 2;
            ldmx4(sb + ST_XH + aoff, aH[0], aH[1], aH[2], aH[3]);
            ldmx4(sb + ST_XL + aoff, aL4[0], aL4[1], aL4[2], aL4[3]);
            uint32_t bH[8][2], bL[8][2];
#pragma unroll
            for (int nt2 = 0; nt2 < 4; nt2++) {
                uint32_t boff = (nt2*16 + (lane & 7) + ((lane >> 4) & 1)*8) * ROWB
                              + (kk*16 + ((lane >> 3) & 1)*8) * 2;
                uint32_t r0, r1, r2, r3;
                ldmx4(sb + ST_BH + boff, r0, r1, r2, r3);
                bH[nt2*2][0]=r0; bH[nt2*2][1]=r1; bH[nt2*2+1][0]=r2; bH[nt2*2+1][1]=r3;
                ldmx4(sb + ST_BL + boff, r0, r1, r2, r3);
                bL[nt2*2][0]=r0; bL[nt2*2][1]=r1; bL[nt2*2+1][0]=r2; bL[nt2*2+1][1]=r3;
            }
#pragma unroll
            for (int nt = 0; nt < 8; nt++) {
                mma16816(acc[nt], aH,  bH[nt][0], bH[nt][1]);
                mma16816(acc[nt], aH,  bL[nt][0], bL[nt][1]);
                mma16816(acc[nt], aL4, bH[nt][0], bH[nt][1]);
            }
        }
    }
    int base = blk * HD * DS;
    int rL = lane >> 2, cc = (lane & 3) * 2;
#pragma unroll
    for (int e = 0; e < 2; e++) {
        int p = pr0 + rL + e*8;
#pragma unroll
        for (int nt = 0; nt < 8; nt++) {
            int n = nt*8 + cc;
            *(float2*)&g_states[base + p*DS + n] =
                make_float2(acc[nt][e*2], acc[nt][e*2+1]);
        }
    }
}

// ---------------- inter-chunk sequential scan ----------------
__global__ __launch_bounds__(256) void k_scan()
{
    int b = blockIdx.x >> 4, h = blockIdx.x & 15;
    int t = threadIdx.x;
    float prev[32];
#pragma unroll
    for (int j = 0; j < 32; j++) prev[j] = 0.f;
    for (int c = 0; c < NCHUNK; c++) {
        int bch = (b * NCHUNK + c) * NH + h;
        int base = bch * HD * DS;
#pragma unroll
        for (int j = 0; j < 32; j++) g_prevs[base + j*256 + t] = prev[j];
        float e = __expf(g_Acs[bch * CHUNKT + 255]);
#pragma unroll
        for (int j = 0; j < 32; j++)
            prev[j] = e * prev[j] + g_states[base + j*256 + t];
    }
}

// ---------------- fused HMMA: Y_diag + Y_off + D-skip + gate -> fp16 [Ah|Al] ----------------
#define SD_CH  0
#define SD_CL  9216
#define SD_BH  18432
#define SD_BL  27648
#define SD_XH  36864
#define SD_XL  55296
#define SD_GH  73728
#define SD_GL  82944
#define SD_ACS 92160
#define SD_DTS 93184
#define SD_SMEM 94208
// Pv (128x64) overlays XH/XL; consumed in phase1 before k-tile staging overwrites them.

__global__ __launch_bounds__(256) void k_ssdout(const float* __restrict__ D_skip)
{
    extern __shared__ __align__(16) char sm8[];
    const uint32_t sb = smem_u32(sm8);
    float* acs = (float*)(sm8 + SD_ACS);
    float* dts = (float*)(sm8 + SD_DTS);

    int blk = blockIdx.x;             // 2048
    int qb = blk & 3;
    int bch = blk >> 2;
    int h = bch & 15, c = (bch >> 4) & 15, b = bch >> 8;
    int t = threadIdx.x;
    int wid = t >> 5, lane = t & 31;
    int m0 = b * LSEQ + c * CHUNKT;
    int q0 = qb * 64;

    acs[t] = g_Acs[bch * CHUNKT + t];
    dts[t] = g_dt[(m0 + t) * NH + h];
    for (int i = t; i < 64*64; i += 256) {
        int q = i >> 6, n = i & 63;
        float v = g_xbc[(size_t)(m0 + q0 + q) * CONVDIM + (DINNER + DS) + n];
        __half hh, ll; hsplit(v, hh, ll);
        *(__half*)(sm8 + SD_CH + q*ROWB + n*2) = hh;
        *(__half*)(sm8 + SD_CL + q*ROWB + n*2) = ll;
    }
    for (int i = t; i < 128*64; i += 256) {
        int p = i >> 6, n = i & 63;
        float v = g_prevs[bch * HD * DS + p*DS + n];
        __half hh, ll; hsplit(v, hh, ll);
        *(__half*)(sm8 + SD_XH + p*ROWB + n*2) = hh;
        *(__half*)(sm8 + SD_XL + p*ROWB + n*2) = ll;
    }
    __syncthreads();

    const int yr0 = (wid >> 1) * 16;
    const int yc0 = (wid & 1) * 64;
    float accY[8][4];
#pragma unroll
    for (int i = 0; i < 8; i++)
#pragma unroll
        for (int j = 0; j < 4; j++) accY[i][j] = 0.f;

    // ---- phase 1: Y = C @ Pv^T ----
#pragma unroll
    for (int kk = 0; kk < 4; kk++) {
        uint32_t aH[4], aL4[4];
        uint32_t aoff = (yr0 + (lane & 15)) * ROWB + (kk*16 + (lane >> 4)*8) * 2;
        ldmx4(sb + SD_CH + aoff, aH[0], aH[1], aH[2], aH[3]);
        ldmx4(sb + SD_CL + aoff, aL4[0], aL4[1], aL4[2], aL4[3]);
        uint32_t bH[8][2], bL[8][2];
#pragma unroll
        for (int nt2 = 0; nt2 < 4; nt2++) {
            uint32_t boff = (yc0 + nt2*16 + (lane & 7) + ((lane >> 4) & 1)*8) * ROWB
                          + (kk*16 + ((lane >> 3) & 1)*8) * 2;
            uint32_t r0, r1, r2, r3;
            ldmx4(sb + SD_XH + boff, r0, r1, r2, r3);
            bH[nt2*2][0]=r0; bH[nt2*2][1]=r1; bH[nt2*2+1][0]=r2; bH[nt2*2+1][1]=r3;
            ldmx4(sb + SD_XL + boff, r0, r1, r2, r3);
            bL[nt2*2][0]=r0; bL[nt2*2][1]=r1; bL[nt2*2+1][0]=r2; bL[nt2*2+1][1]=r3;
        }
#pragma unroll
        for (int nt = 0; nt < 8; nt++) {
            mma16816(accY[nt], aH,  bH[nt][0], bH[nt][1]);
            mma16816(accY[nt], aH,  bL[nt][0], bL[nt][1]);
            mma16816(accY[nt], aL4, bH[nt][0], bH[nt][1]);
        }
    }
    {
        float e0 = __expf(acs[q0 + yr0 + (lane >> 2)]);
        float e1 = __expf(acs[q0 + yr0 + (lane >> 2) + 8]);
#pragma unroll
        for (int nt = 0; nt < 8; nt++) {
            accY[nt][0] *= e0; accY[nt][1] *= e0;
            accY[nt][2] *= e1; accY[nt][3] *= e1;
        }
    }

    // ---- phase 2: Y_diag over k-tiles ----
    const int gr0 = yr0, gc0 = (wid & 1) * 32;
    for (int kt = 0; kt <= qb; kt++) {
        int k0 = kt * 64;
        __syncthreads();
        for (int i = t; i < 64*64; i += 256) {
            int r = i >> 6, n = i & 63;
            float v = g_xbc[(size_t)(m0 + k0 + r) * CONVDIM + DINNER + n];
            __half hh, ll; hsplit(v, hh, ll);
            *(__half*)(sm8 + SD_BH + r*ROWB + n*2) = hh;
            *(__half*)(sm8 + SD_BL + r*ROWB + n*2) = ll;
        }
        for (int i = t; i < 64*128; i += 256) {
            int r = i >> 7, p = i & 127;
            float v = g_xbc[(size_t)(m0 + k0 + r) * CONVDIM + h*HD + p];
            __half hh, ll; hsplit(v, hh, ll);
            *(__half*)(sm8 + SD_XH + p*ROWB + r*2) = hh;
            *(__half*)(sm8 + SD_XL + p*ROWB + r*2) = ll;
        }
        __syncthreads();

        float g[4][4];
#pragma unroll
        for (int i = 0; i < 4; i++)
#pragma unroll
            for (int j = 0; j < 4; j++) g[i][j] = 0.f;
#pragma unroll
        for (int kk = 0; kk < 4; kk++) {
            uint32_t aH[4], aL4[4];
            uint32_t aoff = (gr0 + (lane & 15)) * ROWB + (kk*16 + (lane >> 4)*8) * 2;
            ldmx4(sb + SD_CH + aoff, aH[0], aH[1], aH[2], aH[3]);
            ldmx4(sb + SD_CL + aoff, aL4[0], aL4[1], aL4[2], aL4[3]);
            uint32_t bH[4][2], bL[4][2];
#pragma unroll
            for (int nt2 = 0; nt2 < 2; nt2++) {
                uint32_t boff = (gc0 + nt2*16 + (lane & 7) + ((lane >> 4) & 1)*8) * ROWB
                              + (kk*16 + ((lane >> 3) & 1)*8) * 2;
                uint32_t r0, r1, r2, r3;
                ldmx4(sb + SD_BH + boff, r0, r1, r2, r3);
                bH[nt2*2][0]=r0; bH[nt2*2][1]=r1; bH[nt2*2+1][0]=r2; bH[nt2*2+1][1]=r3;
                ldmx4(sb + SD_BL + boff, r0, r1, r2, r3);
                bL[nt2*2][0]=r0; bL[nt2*2][1]=r1; bL[nt2*2+1][0]=r2; bL[nt2*2+1][1]=r3;
            }
#pragma unroll
            for (int nt = 0; nt < 4; nt++) {
                mma16816(g[nt], aH,  bH[nt][0], bH[nt][1]);
                mma16816(g[nt], aH,  bL[nt][0], bL[nt][1]);
                mma16816(g[nt], aL4, bH[nt][0], bH[nt][1]);
            }
        }
        {
            int rL = lane >> 2, cc = (lane & 3) * 2;
#pragma unroll
            for (int nt = 0; nt < 4; nt++) {
                int klocal = gc0 + nt*8 + cc;
#pragma unroll
                for (int e = 0; e < 2; e++) {
                    int qrow = gr0 + rL + e*8;
                    int qg = q0 + qrow;
#pragma unroll
                    for (int d = 0; d < 2; d++) {
                        int kg = k0 + klocal + d;
                        float v = 0.f;
                        if (kg <= qg)
                            v = g[nt][e*2 + d] * __expf(acs[qg] - acs[kg]) * dts[kg];
                        __half hh, ll; hsplit(v, hh, ll);
                        *(__half*)(sm8 + SD_GH + qrow*ROWB + (klocal + d)*2) = hh;
                        *(__half*)(sm8 + SD_GL + qrow*ROWB + (klocal + d)*2) = ll;
                    }
                }
            }
        }
        __syncthreads();

#pragma unroll
        for (int kk = 0; kk < 4; kk++) {
            uint32_t aH[4], aL4[4];
            uint32_t aoff = (yr0 + (lane & 15)) * ROWB + (kk*16 + (lane >> 4)*8) * 2;
            ldmx4(sb + SD_GH + aoff, aH[0], aH[1], aH[2], aH[3]);
            ldmx4(sb + SD_GL + aoff, aL4[0], aL4[1], aL4[2], aL4[3]);
            uint32_t bH[8][2], bL[8][2];
#pragma unroll
            for (int nt2 = 0; nt2 < 4; nt2++) {
                uint32_t boff = (yc0 + nt2*16 + (lane & 7) + ((lane >> 4) & 1)*8) * ROWB
                              + (kk*16 + ((lane >> 3) & 1)*8) * 2;
                uint32_t r0, r1, r2, r3;
                ldmx4(sb + SD_XH + boff, r0, r1, r2, r3);
                bH[nt2*2][0]=r0; bH[nt2*2][1]=r1; bH[nt2*2+1][0]=r2; bH[nt2*2+1][1]=r3;
                ldmx4(sb + SD_XL + boff, r0, r1, r2, r3);
                bL[nt2*2][0]=r0; bL[nt2*2][1]=r1; bL[nt2*2+1][0]=r2; bL[nt2*2+1][1]=r3;
            }
#pragma unroll
            for (int nt = 0; nt < 8; nt++) {
                mma16816(accY[nt], aH,  bH[nt][0], bH[nt][1]);
                mma16816(accY[nt], aH,  bL[nt][0], bL[nt][1]);
                mma16816(accY[nt], aL4, bH[nt][0], bH[nt][1]);
            }
        }
    }

    // ---- epilogue: D-skip, gate, fp16 [Ah|Al] into g_a3 ----
    float Dh = D_skip[h];
    int rL = lane >> 2, cc = (lane & 3) * 2;
#pragma unroll
    for (int e = 0; e < 2; e++) {
        int m = m0 + q0 + yr0 + rL + e*8;
#pragma unroll
        for (int nt = 0; nt < 8; nt++) {
            int col = h*HD + yc0 + nt*8 + cc;
            float2 xv = *(const float2*)&g_xbc[(size_t)m * CONVDIM + col];
            float2 zz = *(const float2*)&g_proj[(size_t)m * DPROJ + col];
            float y0 = accY[nt][e*2 + 0] + xv.x * Dh;
            float y1 = accY[nt][e*2 + 1] + xv.y * Dh;
            y0 *= zz.x / (1.f + __expf(-zz.x));
            y1 *= zz.y / (1.f + __expf(-zz.y));
            __half h0, l0h, h1, l1h;
            hsplit(y0, h0, l0h); hsplit(y1, h1, l1h);
            __half2 Hh = __halves2half2(h0, h1), Ll = __halves2half2(l0h, l1h);
            __half* basep = g_a3 + (size_t)m * (2*DINNER) + col;
            *(__half2*)(basep)          = Hh;
            *(__half2*)(basep + DINNER) = Ll;
        }
    }
}

// ---------------- launch ----------------
extern "C" void kernel_launch(void* const* d_in, const int* in_sizes, int n_in,
                              void* d_out, int out_size)
{
    const float* x       = (const float*)d_in[0];
    const float* W_in    = (const float*)d_in[1];
    const float* conv_w  = (const float*)d_in[2];
    const float* conv_b  = (const float*)d_in[3];
    const float* A_log   = (const float*)d_in[4];
    const float* dt_bias = (const float*)d_in[5];
    const float* D_skip  = (const float*)d_in[6];
    const float* W_out   = (const float*)d_in[7];
    float* out = (float*)d_out;
    (void)in_sizes; (void)n_in; (void)out_size;

    float *proj = nullptr;
    __half *a3 = nullptr, *b3 = nullptr;
    cudaGetSymbolAddress((void**)&proj, g_proj);
    cudaGetSymbolAddress((void**)&a3, g_a3);
    cudaGetSymbolAddress((void**)&b3, g_b3);

    cudaFuncSetAttribute(k_states, cudaFuncAttributeMaxDynamicSharedMemorySize, ST_SMEM);
    cudaFuncSetAttribute(k_ssdout, cudaFuncAttributeMaxDynamicSharedMemorySize, SD_SMEM);
    cudaFuncSetAttribute(gemm_h3,  cudaFuncAttributeMaxDynamicSharedMemorySize, GSMEM);

    // 1) convert inputs (2-product split), then proj = x @ W_in^T (HMMA)
    k_cvt2<<<(MROWS * (DMODEL/4) + 255)/256, 256>>>((const float4*)x, a3, MROWS, DMODEL, MROWS, 0);
    k_cvt2<<<(NPAD1 * (DMODEL/4) + 255)/256, 256>>>((const float4*)W_in, b3, DPROJ, DMODEL, NPAD1, 1);
    gemm_h3<<<dim3(NPAD1/256, MROWS/128), 512, GSMEM>>>(a3, b3, proj, MROWS, DPROJ, 2*DMODEL);
    // 2) conv + silu
    k_conv<<<dim3(CONVDIM/128, LSEQ/64, BZ), 128>>>(conv_w, conv_b);
    // 3) dt softplus + per-chunk cumsum
    k_dtacs<<<BZ*NCHUNK*NH, 256>>>(dt_bias, A_log);
    // 4) per-chunk states (HMMA, 3-product)
    k_states<<<BZ*NCHUNK*NH, 256, ST_SMEM>>>();
    // 5) inter-chunk scan
    k_scan<<<BZ*NH, 256>>>();
    // 6) fused SSD output (HMMA, 3-product) -> fp16 [Ah|Al] (GEMM2 A operand)
    k_ssdout<<<BZ*NCHUNK*NH*4, 256, SD_SMEM>>>(D_skip);
    // 7) convert W_out, then out = y @ W_out^T (HMMA)
    k_cvt2<<<(DMODEL * (DINNER/4) + 255)/256, 256>>>((const float4*)W_out, b3, DMODEL, DINNER, DMODEL, 1);
    gemm_h3<<<dim3(DMODEL/256, MROWS/128), 512, GSMEM>>>(a3, b3, out, MROWS, DMODEL, 2*DINNER);
}

// round 14
// speedup vs baseline: 1.6352x; 1.0270x over previous
#include <cuda_runtime.h>
#include <cuda_fp16.h>
#include <cstdint>
#include <math.h>

// ---------------- problem constants ----------------
#define BZ      2
#define LSEQ    4096
#define DMODEL  1024
#define DINNER  2048
#define NH      16
#define HD      128
#define DS      64
#define CHUNKT  256
#define NCHUNK  16
#define CONVDIM 2176
#define DPROJ   4240          // DINNER + CONVDIM + NH
#define MROWS   (BZ*LSEQ)     // 8192
#define NPAD1   4352          // ceil(4240/256)*256

// ---------------- scratch (device globals; allocation-free) ----------------
__device__ float g_proj[(size_t)MROWS * DPROJ];
__device__ float g_xbc [(size_t)MROWS * CONVDIM];
__device__ float g_dt  [MROWS * NH];
__device__ float g_Acs [BZ * NCHUNK * NH * CHUNKT];
__device__ float g_states[BZ * NCHUNK * NH * HD * DS];
__device__ float g_prevs [BZ * NCHUNK * NH * HD * DS];
__device__ __half g_a3[(size_t)MROWS * 2 * 2048];               // GEMM A, fp16 [Ah|Al]
__device__ __half g_b3[(size_t)NPAD1 * 2048];                   // GEMM B, fp16 [Bh|Bh]

__device__ __forceinline__ uint32_t smem_u32(const void* p) {
    uint32_t a;
    asm("{ .reg .u64 t; cvta.to.shared.u64 t, %1; cvt.u32.u64 %0, t; }" : "=r"(a) : "l"(p));
    return a;
}
__device__ __forceinline__ void cp16(uint32_t dst, const void* src) {
    asm volatile("cp.async.cg.shared.global [%0], [%1], 16;" :: "r"(dst), "l"(src));
}
__device__ __forceinline__ void cp_commit() { asm volatile("cp.async.commit_group;"); }
template<int NN> __device__ __forceinline__ void cp_wait() {
    asm volatile("cp.async.wait_group %0;" :: "n"(NN));
}
__device__ __forceinline__ void ldmx4(uint32_t addr, uint32_t& r0, uint32_t& r1,
                                      uint32_t& r2, uint32_t& r3) {
    asm volatile("ldmatrix.sync.aligned.m8n8.x4.shared.b16 {%0,%1,%2,%3}, [%4];"
        : "=r"(r0), "=r"(r1), "=r"(r2), "=r"(r3) : "r"(addr));
}
__device__ __forceinline__ void mma16816(float* c, const uint32_t* a, uint32_t b0, uint32_t b1) {
    asm volatile("mma.sync.aligned.m16n8k16.row.col.f32.f16.f16.f32 "
        "{%0,%1,%2,%3}, {%4,%5,%6,%7}, {%8,%9}, {%0,%1,%2,%3};"
        : "+f"(c[0]), "+f"(c[1]), "+f"(c[2]), "+f"(c[3])
        : "r"(a[0]), "r"(a[1]), "r"(a[2]), "r"(a[3]), "r"(b0), "r"(b1));
}
__device__ __forceinline__ void hsplit(float v, __half& h, __half& l) {
    h = __float2half_rn(v);
    l = __float2half_rn(v - __half2float(h));
}

#define ROWB 144   // padded smem row stride for 64-half rows (SSD kernels)

// ---------------- fp32 -> fp16, K doubled ----------------
// isB=0 (A side): [Ah | Al]   isB=1 (B side): [Bh | Bh]
__global__ __launch_bounds__(256) void k_cvt2(
    const float4* __restrict__ src, __half* __restrict__ dst,
    int R, int K, int Rpad, int isB)
{
    int kw = K >> 2;
    int idx = blockIdx.x * 256 + threadIdx.x;
    if (idx >= Rpad * kw) return;
    int r = idx / kw, k4 = idx - r * kw;
    float4 v = make_float4(0.f, 0.f, 0.f, 0.f);
    if (r < R) v = src[(size_t)r * kw + k4];
    __half h0, l0h, h1, l1h, h2, l2h, h3, l3h;
    hsplit(v.x, h0, l0h); hsplit(v.y, h1, l1h);
    hsplit(v.z, h2, l2h); hsplit(v.w, h3, l3h);
    __half2 H0 = __halves2half2(h0, h1), H1 = __halves2half2(h2, h3);
    __half2 L0 = __halves2half2(l0h, l1h), L1 = __halves2half2(l2h, l3h);
    size_t base = (size_t)r * 2 * K + 4 * k4;
    __half2* d0 = (__half2*)(dst + base);
    __half2* d1 = (__half2*)(dst + base + K);
    d0[0] = H0; d0[1] = H1;
    if (isB) { d1[0] = H0; d1[1] = H1; }
    else     { d1[0] = L0; d1[1] = L1; }
}

// ---------------- HMMA GEMM (NT): C[M,N] = A[M,K2] * B[N,K2]^T ----------------
// 128(M) x 256(N) CTA tile, 512 threads (16 warps of 64x32), BK=32 halves,
// 4-stage cp.async pipeline.
#define GPADB 80
#define GSTGA 10240
#define GSTGB2 20480
#define GSTG  (GSTGA + GSTGB2)
#define GSMEM (4 * GSTG)

__global__ __launch_bounds__(512) void gemm_h3(
    const __half* __restrict__ A, const __half* __restrict__ B,
    float* __restrict__ C, int M, int N, int K3)
{
    extern __shared__ __align__(16) char smem_raw[];
    uint32_t sb = smem_u32(smem_raw);
    const int tid = threadIdx.x;
    const int wid = tid >> 5, lane = tid & 31;
    const int m0 = blockIdx.y * 128, n0 = blockIdx.x * 256;
    const int KT = K3 >> 5;
    const int wm = (wid >> 3) * 64, wn = (wid & 7) * 32;

    const int arow = tid >> 2;
    const int aseg = tid & 3;
    const int brow = tid >> 1;
    const int bseg0 = (tid & 1) * 2;

    float acc[4][4][4];
#pragma unroll
    for (int a = 0; a < 4; a++)
#pragma unroll
        for (int b = 0; b < 4; b++)
#pragma unroll
            for (int c = 0; c < 4; c++) acc[a][b][c] = 0.f;

    auto load_stage = [&](int kt) {
        uint32_t sA = sb + (kt & 3) * GSTG;
        uint32_t sB = sA + GSTGA;
        const __half* ga = A + (size_t)(m0 + arow) * K3 + kt * 32;
        const __half* gb = B + (size_t)(n0 + brow) * K3 + kt * 32;
        cp16(sA + arow * GPADB + aseg * 16, ga + aseg * 8);
#pragma unroll
        for (int s = 0; s < 2; s++)
            cp16(sB + brow * GPADB + (bseg0 + s) * 16, gb + (bseg0 + s) * 8);
    };

    load_stage(0); cp_commit();
    load_stage(1); cp_commit();
    load_stage(2); cp_commit();

    for (int kt = 0; kt < KT; kt++) {
        cp_wait<2>();
        __syncthreads();
        if (kt + 3 < KT) load_stage(kt + 3);
        cp_commit();
        uint32_t sA = sb + (kt & 3) * GSTG;
        uint32_t sB = sA + GSTGA;
#pragma unroll
        for (int kk = 0; kk < 2; kk++) {
            uint32_t a[4][4], b[4][2];
#pragma unroll
            for (int mt = 0; mt < 4; mt++) {
                uint32_t addr = sA + (wm + mt * 16 + (lane & 15)) * GPADB
                              + (kk * 16 + (lane >> 4) * 8) * 2;
                ldmx4(addr, a[mt][0], a[mt][1], a[mt][2], a[mt][3]);
            }
#pragma unroll
            for (int nt2 = 0; nt2 < 2; nt2++) {
                uint32_t r0, r1, r2, r3;
                int n = wn + nt2 * 16 + (lane & 7) + ((lane >> 4) & 1) * 8;
                int kc = kk * 16 + ((lane >> 3) & 1) * 8;
                ldmx4(sB + n * GPADB + kc * 2, r0, r1, r2, r3);
                b[nt2*2][0] = r0; b[nt2*2][1] = r1;
                b[nt2*2+1][0] = r2; b[nt2*2+1][1] = r3;
            }
#pragma unroll
            for (int mt = 0; mt < 4; mt++)
#pragma unroll
                for (int nt = 0; nt < 4; nt++)
                    mma16816(acc[mt][nt], a[mt], b[nt][0], b[nt][1]);
        }
    }

#pragma unroll
    for (int mt = 0; mt < 4; mt++) {
        int r0 = m0 + wm + mt * 16 + (lane >> 2);
#pragma unroll
        for (int nt = 0; nt < 4; nt++) {
            int cb = n0 + wn + nt * 8 + (lane & 3) * 2;
            if (cb < N) {
                *(float2*)(C + (size_t)r0 * N + cb) =
                    make_float2(acc[mt][nt][0], acc[mt][nt][1]);
                *(float2*)(C + (size_t)(r0 + 8) * N + cb) =
                    make_float2(acc[mt][nt][2], acc[mt][nt][3]);
            }
        }
    }
}

// ---------------- depthwise causal conv (D_CONV=4) + bias + SiLU ----------------
__global__ __launch_bounds__(128) void k_conv(
    const float* __restrict__ cw, const float* __restrict__ cb)
{
    int c = blockIdx.x * 128 + threadIdx.x;
    int b = blockIdx.z;
    int l0 = blockIdx.y * 64;
    float w0 = cw[c*4+0], w1 = cw[c*4+1], w2 = cw[c*4+2], w3 = cw[c*4+3];
    float bias = cb[c];
    const float* pp = g_proj + (size_t)b * LSEQ * DPROJ + DINNER + c;
    float* op = g_xbc + (size_t)b * LSEQ * CONVDIM + c;
    float xm3 = 0.f, xm2 = 0.f, xm1 = 0.f;
    if (l0 >= 3) {
        xm3 = pp[(size_t)(l0-3) * DPROJ];
        xm2 = pp[(size_t)(l0-2) * DPROJ];
        xm1 = pp[(size_t)(l0-1) * DPROJ];
    }
#pragma unroll 4
    for (int i = 0; i < 64; i++) {
        int l = l0 + i;
        float xc = pp[(size_t)l * DPROJ];
        float s = w3*xc + w2*xm1 + w1*xm2 + w0*xm3 + bias;
        float sig = 1.f / (1.f + expf(-s));
        op[(size_t)l * CONVDIM] = s * sig;
        xm3 = xm2; xm2 = xm1; xm1 = xc;
    }
}

// ---------------- dt = softplus(...) fused with per-chunk cumsum of dt*A ----------------
__global__ __launch_bounds__(256) void k_dtacs(
    const float* __restrict__ dt_bias, const float* __restrict__ A_log)
{
    int blk = blockIdx.x;
    int h = blk & 15, c = (blk >> 4) & 15, b = blk >> 8;
    int t = threadIdx.x;
    int m = b * LSEQ + c * CHUNKT + t;
    float v = g_proj[(size_t)m * DPROJ + (DINNER + CONVDIM) + h] + dt_bias[h];
    float dt = (v > 20.f) ? v : log1pf(expf(v));
    g_dt[m * NH + h] = dt;
    float A = -expf(A_log[h]);
    __shared__ float s[CHUNKT];
    s[t] = dt * A;
    __syncthreads();
    for (int off = 1; off < CHUNKT; off <<= 1) {
        float u = (t >= off) ? s[t - off] : 0.f;
        __syncthreads();
        s[t] += u;
        __syncthreads();
    }
    g_Acs[blk * CHUNKT + t] = s[t];
}

// ---------------- per-chunk states (HMMA, 2-product): S = XT * (w.B)h ----------------
#define ST_XH 0
#define ST_XL 18432
#define ST_BH 36864
#define ST_SC 46080
#define ST_SMEM 47104

__global__ __launch_bounds__(256) void k_states()
{
    extern __shared__ __align__(16) char sm9[];
    const uint32_t sb = smem_u32(sm9);
    float* sc = (float*)(sm9 + ST_SC);
    int blk = blockIdx.x;
    int h = blk & 15, c = (blk >> 4) & 15, b = blk >> 8;
    int t = threadIdx.x;
    int wid = t >> 5, lane = t & 31;
    int m0 = b * LSEQ + c * CHUNKT;
    float aL = g_Acs[blk * CHUNKT + 255];
    sc[t] = g_dt[(m0 + t) * NH + h] * __expf(aL - g_Acs[blk * CHUNKT + t]);

    const int pr0 = wid * 16;
    float acc[8][4];
#pragma unroll
    for (int i = 0; i < 8; i++)
#pragma unroll
        for (int j = 0; j < 4; j++) acc[i][j] = 0.f;

    for (int kt = 0; kt < 4; kt++) {
        int k0 = kt * 64;
        __syncthreads();
        for (int i = t; i < 64*128; i += 256) {
            int r = i >> 7, p = i & 127;
            float v = g_xbc[(size_t)(m0 + k0 + r) * CONVDIM + h*HD + p];
            __half hh, ll; hsplit(v, hh, ll);
            *(__half*)(sm9 + ST_XH + p*ROWB + r*2) = hh;
            *(__half*)(sm9 + ST_XL + p*ROWB + r*2) = ll;
        }
        for (int i = t; i < 64*64; i += 256) {
            int r = i >> 6, n = i & 63;
            float v = g_xbc[(size_t)(m0 + k0 + r) * CONVDIM + DINNER + n] * sc[k0 + r];
            *(__half*)(sm9 + ST_BH + n*ROWB + r*2) = __float2half_rn(v);
        }
        __syncthreads();
#pragma unroll
        for (int kk = 0; kk < 4; kk++) {
            uint32_t aH[4], aL4[4];
            uint32_t aoff = (pr0 + (lane & 15)) * ROWB + (kk*16 + (lane >> 4)*8) * 2;
            ldmx4(sb + ST_XH + aoff, aH[0], aH[1], aH[2], aH[3]);
            ldmx4(sb + ST_XL + aoff, aL4[0], aL4[1], aL4[2], aL4[3]);
            uint32_t bH[8][2];
#pragma unroll
            for (int nt2 = 0; nt2 < 4; nt2++) {
                uint32_t boff = (nt2*16 + (lane & 7) + ((lane >> 4) & 1)*8) * ROWB
                              + (kk*16 + ((lane >> 3) & 1)*8) * 2;
                uint32_t r0, r1, r2, r3;
                ldmx4(sb + ST_BH + boff, r0, r1, r2, r3);
                bH[nt2*2][0]=r0; bH[nt2*2][1]=r1; bH[nt2*2+1][0]=r2; bH[nt2*2+1][1]=r3;
            }
#pragma unroll
            for (int nt = 0; nt < 8; nt++) {
                mma16816(acc[nt], aH,  bH[nt][0], bH[nt][1]);
                mma16816(acc[nt], aL4, bH[nt][0], bH[nt][1]);
            }
        }
    }
    int base = blk * HD * DS;
    int rL = lane >> 2, cc = (lane & 3) * 2;
#pragma unroll
    for (int e = 0; e < 2; e++) {
        int p = pr0 + rL + e*8;
#pragma unroll
        for (int nt = 0; nt < 8; nt++) {
            int n = nt*8 + cc;
            *(float2*)&g_states[base + p*DS + n] =
                make_float2(acc[nt][e*2], acc[nt][e*2+1]);
        }
    }
}

// ---------------- inter-chunk sequential scan ----------------
__global__ __launch_bounds__(256) void k_scan()
{
    int b = blockIdx.x >> 4, h = blockIdx.x & 15;
    int t = threadIdx.x;
    float prev[32];
#pragma unroll
    for (int j = 0; j < 32; j++) prev[j] = 0.f;
    for (int c = 0; c < NCHUNK; c++) {
        int bch = (b * NCHUNK + c) * NH + h;
        int base = bch * HD * DS;
#pragma unroll
        for (int j = 0; j < 32; j++) g_prevs[base + j*256 + t] = prev[j];
        float e = __expf(g_Acs[bch * CHUNKT + 255]);
#pragma unroll
        for (int j = 0; j < 32; j++)
            prev[j] = e * prev[j] + g_states[base + j*256 + t];
    }
}

// ---------------- fused HMMA (2-product): Y_diag + Y_off + D-skip + gate -> fp16 [Ah|Al] ----------------
#define SD_CH  0
#define SD_CL  9216
#define SD_BH  18432
#define SD_XH  27648          // 128 rows (also holds Pv-hi in phase 1)
#define SD_GH  46080
#define SD_GL  55296
#define SD_ACS 64512
#define SD_DTS 65536
#define SD_SMEM 66560

__global__ __launch_bounds__(256) void k_ssdout(const float* __restrict__ D_skip)
{
    extern __shared__ __align__(16) char sm8[];
    const uint32_t sb = smem_u32(sm8);
    float* acs = (float*)(sm8 + SD_ACS);
    float* dts = (float*)(sm8 + SD_DTS);

    int blk = blockIdx.x;             // 2048
    int qb = blk & 3;
    int bch = blk >> 2;
    int h = bch & 15, c = (bch >> 4) & 15, b = bch >> 8;
    int t = threadIdx.x;
    int wid = t >> 5, lane = t & 31;
    int m0 = b * LSEQ + c * CHUNKT;
    int q0 = qb * 64;

    acs[t] = g_Acs[bch * CHUNKT + t];
    dts[t] = g_dt[(m0 + t) * NH + h];
    // stage C [64q][64n] hi/lo (A-side keeps lo)
    for (int i = t; i < 64*64; i += 256) {
        int q = i >> 6, n = i & 63;
        float v = g_xbc[(size_t)(m0 + q0 + q) * CONVDIM + (DINNER + DS) + n];
        __half hh, ll; hsplit(v, hh, ll);
        *(__half*)(sm8 + SD_CH + q*ROWB + n*2) = hh;
        *(__half*)(sm8 + SD_CL + q*ROWB + n*2) = ll;
    }
    // stage Pv [128p][64n] hi only into X slot
    for (int i = t; i < 128*64; i += 256) {
        int p = i >> 6, n = i & 63;
        float v = g_prevs[bch * HD * DS + p*DS + n];
        *(__half*)(sm8 + SD_XH + p*ROWB + n*2) = __float2half_rn(v);
    }
    __syncthreads();

    const int yr0 = (wid >> 1) * 16;
    const int yc0 = (wid & 1) * 64;
    float accY[8][4];
#pragma unroll
    for (int i = 0; i < 8; i++)
#pragma unroll
        for (int j = 0; j < 4; j++) accY[i][j] = 0.f;

    // ---- phase 1: Y = C @ Pv^T ----
#pragma unroll
    for (int kk = 0; kk < 4; kk++) {
        uint32_t aH[4], aL4[4];
        uint32_t aoff = (yr0 + (lane & 15)) * ROWB + (kk*16 + (lane >> 4)*8) * 2;
        ldmx4(sb + SD_CH + aoff, aH[0], aH[1], aH[2], aH[3]);
        ldmx4(sb + SD_CL + aoff, aL4[0], aL4[1], aL4[2], aL4[3]);
        uint32_t bH[8][2];
#pragma unroll
        for (int nt2 = 0; nt2 < 4; nt2++) {
            uint32_t boff = (yc0 + nt2*16 + (lane & 7) + ((lane >> 4) & 1)*8) * ROWB
                          + (kk*16 + ((lane >> 3) & 1)*8) * 2;
            uint32_t r0, r1, r2, r3;
            ldmx4(sb + SD_XH + boff, r0, r1, r2, r3);
            bH[nt2*2][0]=r0; bH[nt2*2][1]=r1; bH[nt2*2+1][0]=r2; bH[nt2*2+1][1]=r3;
        }
#pragma unroll
        for (int nt = 0; nt < 8; nt++) {
            mma16816(accY[nt], aH,  bH[nt][0], bH[nt][1]);
            mma16816(accY[nt], aL4, bH[nt][0], bH[nt][1]);
        }
    }
    {
        float e0 = __expf(acs[q0 + yr0 + (lane >> 2)]);
        float e1 = __expf(acs[q0 + yr0 + (lane >> 2) + 8]);
#pragma unroll
        for (int nt = 0; nt < 8; nt++) {
            accY[nt][0] *= e0; accY[nt][1] *= e0;
            accY[nt][2] *= e1; accY[nt][3] *= e1;
        }
    }

    // ---- phase 2: Y_diag over k-tiles ----
    const int gr0 = yr0, gc0 = (wid & 1) * 32;
    for (int kt = 0; kt <= qb; kt++) {
        int k0 = kt * 64;
        __syncthreads();
        // stage B [64k][64n] hi only
        for (int i = t; i < 64*64; i += 256) {
            int r = i >> 6, n = i & 63;
            float v = g_xbc[(size_t)(m0 + k0 + r) * CONVDIM + DINNER + n];
            *(__half*)(sm8 + SD_BH + r*ROWB + n*2) = __float2half_rn(v);
        }
        // stage XT (transpose) [128p][64k] hi only
        for (int i = t; i < 64*128; i += 256) {
            int r = i >> 7, p = i & 127;
            float v = g_xbc[(size_t)(m0 + k0 + r) * CONVDIM + h*HD + p];
            *(__half*)(sm8 + SD_XH + p*ROWB + r*2) = __float2half_rn(v);
        }
        __syncthreads();

        // stage1: G = C @ B^T (2-product)
        float g[4][4];
#pragma unroll
        for (int i = 0; i < 4; i++)
#pragma unroll
            for (int j = 0; j < 4; j++) g[i][j] = 0.f;
#pragma unroll
        for (int kk = 0; kk < 4; kk++) {
            uint32_t aH[4], aL4[4];
            uint32_t aoff = (gr0 + (lane & 15)) * ROWB + (kk*16 + (lane >> 4)*8) * 2;
            ldmx4(sb + SD_CH + aoff, aH[0], aH[1], aH[2], aH[3]);
            ldmx4(sb + SD_CL + aoff, aL4[0], aL4[1], aL4[2], aL4[3]);
            uint32_t bH[4][2];
#pragma unroll
            for (int nt2 = 0; nt2 < 2; nt2++) {
                uint32_t boff = (gc0 + nt2*16 + (lane & 7) + ((lane >> 4) & 1)*8) * ROWB
                              + (kk*16 + ((lane >> 3) & 1)*8) * 2;
                uint32_t r0, r1, r2, r3;
                ldmx4(sb + SD_BH + boff, r0, r1, r2, r3);
                bH[nt2*2][0]=r0; bH[nt2*2][1]=r1; bH[nt2*2+1][0]=r2; bH[nt2*2+1][1]=r3;
            }
#pragma unroll
            for (int nt = 0; nt < 4; nt++) {
                mma16816(g[nt], aH,  bH[nt][0], bH[nt][1]);
                mma16816(g[nt], aL4, bH[nt][0], bH[nt][1]);
            }
        }
        // mask + decay + dt; split hi/lo (G is the A-side of stage2)
        {
            int rL = lane >> 2, cc = (lane & 3) * 2;
#pragma unroll
            for (int nt = 0; nt < 4; nt++) {
                int klocal = gc0 + nt*8 + cc;
#pragma unroll
                for (int e = 0; e < 2; e++) {
                    int qrow = gr0 + rL + e*8;
                    int qg = q0 + qrow;
#pragma unroll
                    for (int d = 0; d < 2; d++) {
                        int kg = k0 + klocal + d;
                        float v = 0.f;
                        if (kg <= qg)
                            v = g[nt][e*2 + d] * __expf(acs[qg] - acs[kg]) * dts[kg];
                        __half hh, ll; hsplit(v, hh, ll);
                        *(__half*)(sm8 + SD_GH + qrow*ROWB + (klocal + d)*2) = hh;
                        *(__half*)(sm8 + SD_GL + qrow*ROWB + (klocal + d)*2) = ll;
                    }
                }
            }
        }
        __syncthreads();

        // stage2: Y += G @ XT^T (2-product)
#pragma unroll
        for (int kk = 0; kk < 4; kk++) {
            uint32_t aH[4], aL4[4];
            uint32_t aoff = (yr0 + (lane & 15)) * ROWB + (kk*16 + (lane >> 4)*8) * 2;
            ldmx4(sb + SD_GH + aoff, aH[0], aH[1], aH[2], aH[3]);
            ldmx4(sb + SD_GL + aoff, aL4[0], aL4[1], aL4[2], aL4[3]);
            uint32_t bH[8][2];
#pragma unroll
            for (int nt2 = 0; nt2 < 4; nt2++) {
                uint32_t boff = (yc0 + nt2*16 + (lane & 7) + ((lane >> 4) & 1)*8) * ROWB
                              + (kk*16 + ((lane >> 3) & 1)*8) * 2;
                uint32_t r0, r1, r2, r3;
                ldmx4(sb + SD_XH + boff, r0, r1, r2, r3);
                bH[nt2*2][0]=r0; bH[nt2*2][1]=r1; bH[nt2*2+1][0]=r2; bH[nt2*2+1][1]=r3;
            }
#pragma unroll
            for (int nt = 0; nt < 8; nt++) {
                mma16816(accY[nt], aH,  bH[nt][0], bH[nt][1]);
                mma16816(accY[nt], aL4, bH[nt][0], bH[nt][1]);
            }
        }
    }

    // ---- epilogue: D-skip, gate, fp16 [Ah|Al] into g_a3 ----
    float Dh = D_skip[h];
    int rL = lane >> 2, cc = (lane & 3) * 2;
#pragma unroll
    for (int e = 0; e < 2; e++) {
        int m = m0 + q0 + yr0 + rL + e*8;
#pragma unroll
        for (int nt = 0; nt < 8; nt++) {
            int col = h*HD + yc0 + nt*8 + cc;
            float2 xv = *(const float2*)&g_xbc[(size_t)m * CONVDIM + col];
            float2 zz = *(const float2*)&g_proj[(size_t)m * DPROJ + col];
            float y0 = accY[nt][e*2 + 0] + xv.x * Dh;
            float y1 = accY[nt][e*2 + 1] + xv.y * Dh;
            y0 *= zz.x / (1.f + __expf(-zz.x));
            y1 *= zz.y / (1.f + __expf(-zz.y));
            __half h0, l0h, h1, l1h;
            hsplit(y0, h0, l0h); hsplit(y1, h1, l1h);
            __half2 Hh = __halves2half2(h0, h1), Ll = __halves2half2(l0h, l1h);
            __half* basep = g_a3 + (size_t)m * (2*DINNER) + col;
            *(__half2*)(basep)          = Hh;
            *(__half2*)(basep + DINNER) = Ll;
        }
    }
}

// ---------------- launch ----------------
extern "C" void kernel_launch(void* const* d_in, const int* in_sizes, int n_in,
                              void* d_out, int out_size)
{
    const float* x       = (const float*)d_in[0];
    const float* W_in    = (const float*)d_in[1];
    const float* conv_w  = (const float*)d_in[2];
    const float* conv_b  = (const float*)d_in[3];
    const float* A_log   = (const float*)d_in[4];
    const float* dt_bias = (const float*)d_in[5];
    const float* D_skip  = (const float*)d_in[6];
    const float* W_out   = (const float*)d_in[7];
    float* out = (float*)d_out;
    (void)in_sizes; (void)n_in; (void)out_size;

    float *proj = nullptr;
    __half *a3 = nullptr, *b3 = nullptr;
    cudaGetSymbolAddress((void**)&proj, g_proj);
    cudaGetSymbolAddress((void**)&a3, g_a3);
    cudaGetSymbolAddress((void**)&b3, g_b3);

    cudaFuncSetAttribute(k_states, cudaFuncAttributeMaxDynamicSharedMemorySize, ST_SMEM);
    cudaFuncSetAttribute(k_ssdout, cudaFuncAttributeMaxDynamicSharedMemorySize, SD_SMEM);
    cudaFuncSetAttribute(gemm_h3,  cudaFuncAttributeMaxDynamicSharedMemorySize, GSMEM);

    // 1) convert inputs (2-product split), then proj = x @ W_in^T (HMMA)
    k_cvt2<<<(MROWS * (DMODEL/4) + 255)/256, 256>>>((const float4*)x, a3, MROWS, DMODEL, MROWS, 0);
    k_cvt2<<<(NPAD1 * (DMODEL/4) + 255)/256, 256>>>((const float4*)W_in, b3, DPROJ, DMODEL, NPAD1, 1);
    gemm_h3<<<dim3(NPAD1/256, MROWS/128), 512, GSMEM>>>(a3, b3, proj, MROWS, DPROJ, 2*DMODEL);
    // 2) conv + silu
    k_conv<<<dim3(CONVDIM/128, LSEQ/64, BZ), 128>>>(conv_w, conv_b);
    // 3) dt softplus + per-chunk cumsum
    k_dtacs<<<BZ*NCHUNK*NH, 256>>>(dt_bias, A_log);
    // 4) per-chunk states (HMMA, 2-product)
    k_states<<<BZ*NCHUNK*NH, 256, ST_SMEM>>>();
    // 5) inter-chunk scan
    k_scan<<<BZ*NH, 256>>>();
    // 6) fused SSD output (HMMA, 2-product) -> fp16 [Ah|Al] (GEMM2 A operand)
    k_ssdout<<<BZ*NCHUNK*NH*4, 256, SD_SMEM>>>(D_skip);
    // 7) convert W_out, then out = y @ W_out^T (HMMA)
    k_cvt2<<<(DMODEL * (DINNER/4) + 255)/256, 256>>>((const float4*)W_out, b3, DMODEL, DINNER, DMODEL, 1);
    gemm_h3<<<dim3(DMODEL/256, MROWS/128), 512, GSMEM>>>(a3, b3, out, MROWS, DMODEL, 2*DINNER);
}